// round 5
// baseline (speedup 1.0000x reference)
#include <cuda_runtime.h>
#include <math.h>
#include <stdint.h>

#define B_    2
#define T_    2048
#define C_    2048
#define H_    16
#define KVH_  4
#define D_    128
#define GROUPS_ (H_/KVH_)
#define EPS_  1.1920929e-07f

#define GK    2048          // K dim of all big GEMMs
#define NIT   64            // GK / 32

// ---------------- scratch (device globals; no cudaMalloc allowed) ----------
__device__ float g_qt  [B_*T_*H_*D_];     // [B, H, T, D]  rope+rms+scale
__device__ float g_kt  [B_*T_*KVH_*D_];   // [B, KVH, T, D] rope+rms
__device__ float g_vlin[B_*T_*KVH_*D_];   // [B*T, KVH*D]
__device__ float g_y   [B_*T_*H_*D_];     // [B, T, H*D]

// ---------------------------------------------------------------------------
// tf32 helpers
// ---------------------------------------------------------------------------
__device__ __forceinline__ unsigned f2tf(float f) {
    unsigned u;
    asm("cvt.rna.tf32.f32 %0, %1;" : "=r"(u) : "f"(f));
    return u;
}

__device__ __forceinline__ void mma8(float* d, const unsigned* a, const unsigned* b) {
    asm volatile(
        "mma.sync.aligned.m16n8k8.row.col.f32.tf32.tf32.f32 "
        "{%0,%1,%2,%3}, {%4,%5,%6,%7}, {%8,%9}, {%0,%1,%2,%3};\n"
        : "+f"(d[0]), "+f"(d[1]), "+f"(d[2]), "+f"(d[3])
        : "r"(a[0]), "r"(a[1]), "r"(a[2]), "r"(a[3]), "r"(b[0]), "r"(b[1]));
}

// ---------------------------------------------------------------------------
// GEMM machinery: 128x128 CTA tile, BK=32, 256 thr = 8 warps (4M x 2N),
// warp tile 32x64, smem double-buffered, k-PERMUTED layout:
// within each 8-col k-group, logical col c stored at 2*(c%4)+(c/4), so the
// fragment pair (t, t+4) is one LDS.64. Row stride 40 words (pair-bank 4g+t,
// conflict-free).
// ---------------------------------------------------------------------------
#define GST 40                         // smem row stride (words)

__device__ __forceinline__ void ldg_tile(const float* Ab, const float* Wb, int k0,
                                         int tid, float4* ra, float4* rw) {
    #pragma unroll
    for (int l = 0; l < 2; l++) {
        int G  = tid + l * 256;         // 0..511 : 128 rows x 4 k-groups
        int r  = G >> 2;
        int c8 = (G & 3) * 8;
        ra[2*l]   = *(const float4*)(Ab + (size_t)r * GK + k0 + c8);
        ra[2*l+1] = *(const float4*)(Ab + (size_t)r * GK + k0 + c8 + 4);
        rw[2*l]   = *(const float4*)(Wb + (size_t)r * GK + k0 + c8);
        rw[2*l+1] = *(const float4*)(Wb + (size_t)r * GK + k0 + c8 + 4);
    }
}

__device__ __forceinline__ void sts_tile(unsigned* As, unsigned* Ws, int tid,
                                         const float4* ra, const float4* rw) {
    #pragma unroll
    for (int l = 0; l < 2; l++) {
        int G  = tid + l * 256;
        int r  = G >> 2;
        int base = r * GST + (G & 3) * 8;
        float4 a0 = ra[2*l], a1 = ra[2*l+1];
        *(uint2*)&As[base]     = make_uint2(f2tf(a0.x), f2tf(a1.x));
        *(uint2*)&As[base + 2] = make_uint2(f2tf(a0.y), f2tf(a1.y));
        *(uint2*)&As[base + 4] = make_uint2(f2tf(a0.z), f2tf(a1.z));
        *(uint2*)&As[base + 6] = make_uint2(f2tf(a0.w), f2tf(a1.w));
        float4 w0 = rw[2*l], w1 = rw[2*l+1];
        *(uint2*)&Ws[base]     = make_uint2(f2tf(w0.x), f2tf(w1.x));
        *(uint2*)&Ws[base + 2] = make_uint2(f2tf(w0.y), f2tf(w1.y));
        *(uint2*)&Ws[base + 4] = make_uint2(f2tf(w0.z), f2tf(w1.z));
        *(uint2*)&Ws[base + 6] = make_uint2(f2tf(w0.w), f2tf(w1.w));
    }
}

__device__ __forceinline__ void mma_tile(const unsigned* As, const unsigned* Ws,
                                         int wm, int wn, int g, int t,
                                         float acc[2][8][4]) {
    #pragma unroll
    for (int kk4 = 0; kk4 < 4; kk4++) {
        const int ko = kk4 * 8 + 2 * t;
        unsigned a[2][4], b[8][2];
        #pragma unroll
        for (int mi = 0; mi < 2; mi++) {
            int r = wm + mi * 16;
            uint2 v0 = *(const uint2*)&As[(r + g)     * GST + ko];
            uint2 v1 = *(const uint2*)&As[(r + g + 8) * GST + ko];
            a[mi][0] = v0.x; a[mi][2] = v0.y;
            a[mi][1] = v1.x; a[mi][3] = v1.y;
        }
        #pragma unroll
        for (int j = 0; j < 8; j++) {
            uint2 v = *(const uint2*)&Ws[(wn + j * 8 + g) * GST + ko];
            b[j][0] = v.x; b[j][1] = v.y;
        }
        #pragma unroll
        for (int mi = 0; mi < 2; mi++)
            #pragma unroll
            for (int j = 0; j < 8; j++)
                mma8(acc[mi][j], a[mi], b[j]);
    }
}

#define GEMM_MAINLOOP(Ab, Wb)                                                  \
    float acc[2][8][4];                                                        \
    _Pragma("unroll")                                                          \
    for (int mi = 0; mi < 2; mi++)                                             \
        _Pragma("unroll")                                                      \
        for (int j = 0; j < 8; j++)                                            \
            _Pragma("unroll")                                                  \
            for (int c = 0; c < 4; c++) acc[mi][j][c] = 0.f;                   \
    {                                                                          \
        float4 ra[4], rw[4];                                                   \
        ldg_tile(Ab, Wb, 0, tid, ra, rw);                                      \
        sts_tile(As0, Ws0, tid, ra, rw);                                       \
        __syncthreads();                                                       \
        for (int it = 0; it < NIT; it++) {                                     \
            unsigned* Ac = (it & 1) ? As1 : As0;                               \
            unsigned* Wc = (it & 1) ? Ws1 : Ws0;                               \
            unsigned* An = (it & 1) ? As0 : As1;                               \
            unsigned* Wn = (it & 1) ? Ws0 : Ws1;                               \
            if (it + 1 < NIT) ldg_tile(Ab, Wb, (it + 1) * 32, tid, ra, rw);    \
            mma_tile(Ac, Wc, wm, wn, g, t, acc);                               \
            if (it + 1 < NIT) sts_tile(An, Wn, tid, ra, rw);                   \
            __syncthreads();                                                   \
        }                                                                      \
    }

// smem: 4 buffers of 128*GST words
#define GEMM_SMEM (4 * 128 * GST * 4)

// ---------------------------------------------------------------------------
// Fused QKV projection + RoPE + RMSNorm epilogue.
// grid = (24, 32): nb<16 -> Q head nb; [16,20) -> K head; [20,24) -> V head.
// ---------------------------------------------------------------------------
__global__ __launch_bounds__(256) void qkv_gemm(
    const float* __restrict__ x,
    const float* __restrict__ Wq, const float* __restrict__ Wk,
    const float* __restrict__ Wv,
    const float* __restrict__ cosb, const float* __restrict__ sinb,
    float* __restrict__ qt, float* __restrict__ kt, float* __restrict__ vlin)
{
    extern __shared__ unsigned sm[];
    unsigned* As0 = sm;
    unsigned* Ws0 = sm + 128 * GST;
    unsigned* As1 = sm + 2 * 128 * GST;
    unsigned* Ws1 = sm + 3 * 128 * GST;

    const int tid  = threadIdx.x;
    const int lane = tid & 31;
    const int wid  = tid >> 5;
    const int g    = lane >> 2;
    const int t    = lane & 3;
    const int wm = (wid & 3) * 32;
    const int wn = (wid >> 2) * 64;
    const int m0 = blockIdx.y * 128;
    const int nb = blockIdx.x;

    const float* W;
    int nrow;
    if (nb < 16)      { W = Wq; nrow = nb * 128; }
    else if (nb < 20) { W = Wk; nrow = (nb - 16) * 128; }
    else              { W = Wv; nrow = (nb - 20) * 128; }
    const float* Ab = x + (size_t)m0 * GK;
    const float* Wb = W + (size_t)nrow * GK;

    GEMM_MAINLOOP(Ab, Wb)

    if (nb >= 20) {
        const int n0 = (nb - 20) * 128;
        #pragma unroll
        for (int mi = 0; mi < 2; mi++) {
            int r0 = m0 + wm + mi * 16 + g;
            #pragma unroll
            for (int j = 0; j < 8; j++) {
                int cc = n0 + wn + j * 8 + 2 * t;
                *(float2*)(vlin + (size_t)r0 * (KVH_ * D_) + cc) =
                    make_float2(acc[mi][j][0], acc[mi][j][1]);
                *(float2*)(vlin + (size_t)(r0 + 8) * (KVH_ * D_) + cc) =
                    make_float2(acc[mi][j][2], acc[mi][j][3]);
            }
        }
        return;
    }

    // ---- Q/K: stage acc -> smem, then rope + rmsnorm + transpose ----
    float* St = (float*)sm;   // 128 rows x stride 132 = 67584 B <= GEMM_SMEM
    #pragma unroll
    for (int mi = 0; mi < 2; mi++) {
        int r0 = wm + mi * 16 + g;
        #pragma unroll
        for (int j = 0; j < 8; j++) {
            int cc = wn + j * 8 + 2 * t;
            St[r0 * 132 + cc]           = acc[mi][j][0];
            St[r0 * 132 + cc + 1]       = acc[mi][j][1];
            St[(r0 + 8) * 132 + cc]     = acc[mi][j][2];
            St[(r0 + 8) * 132 + cc + 1] = acc[mi][j][3];
        }
    }
    __syncthreads();

    {
        const int r  = tid >> 1;
        const int hf = tid & 1;
        const int m  = m0 + r;
        const int bb = m >> 11;
        const int tt = m & (T_ - 1);
        const float scale = (nb < 16) ? 0.08838834764831845f : 1.0f;

        const float* cr = cosb + tt * 64 + hf * 32;
        const float* sr = sinb + tt * 64 + hf * 32;
        const float* x1p = St + r * 132 + hf * 32;
        const float* x2p = x1p + 64;

        float o1[32], o2[32];
        float ss = 0.f;
        #pragma unroll
        for (int jj = 0; jj < 32; jj += 4) {
            float4 x1 = *(const float4*)(x1p + jj);
            float4 x2 = *(const float4*)(x2p + jj);
            float4 cv = *(const float4*)(cr + jj);
            float4 sv = *(const float4*)(sr + jj);
            float a0 = x1.x * cv.x + x2.x * sv.x, b0 = x2.x * cv.x - x1.x * sv.x;
            float a1 = x1.y * cv.y + x2.y * sv.y, b1 = x2.y * cv.y - x1.y * sv.y;
            float a2 = x1.z * cv.z + x2.z * sv.z, b2 = x2.z * cv.z - x1.z * sv.z;
            float a3 = x1.w * cv.w + x2.w * sv.w, b3 = x2.w * cv.w - x1.w * sv.w;
            o1[jj] = a0; o1[jj+1] = a1; o1[jj+2] = a2; o1[jj+3] = a3;
            o2[jj] = b0; o2[jj+1] = b1; o2[jj+2] = b2; o2[jj+3] = b3;
            ss += a0*a0 + b0*b0 + a1*a1 + b1*b1 + a2*a2 + b2*b2 + a3*a3 + b3*b3;
        }
        ss += __shfl_xor_sync(0xffffffffu, ss, 1);
        const float rr = rsqrtf(ss * (1.f / 128.f) + EPS_) * scale;

        float* ob;
        if (nb < 16)
            ob = qt + (((size_t)(bb * H_ + nb) * T_ + tt) * D_);
        else
            ob = kt + (((size_t)(bb * KVH_ + (nb - 16)) * T_ + tt) * D_);

        #pragma unroll
        for (int jj = 0; jj < 32; jj += 4) {
            *(float4*)(ob + hf * 32 + jj) = make_float4(
                o1[jj] * rr, o1[jj+1] * rr, o1[jj+2] * rr, o1[jj+3] * rr);
            *(float4*)(ob + 64 + hf * 32 + jj) = make_float4(
                o2[jj] * rr, o2[jj+1] * rr, o2[jj+2] * rr, o2[jj+3] * rr);
        }
    }
}

// ---------------------------------------------------------------------------
// Plain GEMM (output projection)
// ---------------------------------------------------------------------------
__global__ __launch_bounds__(256) void out_gemm(
    const float* __restrict__ A, const float* __restrict__ W,
    float* __restrict__ C, int N)
{
    extern __shared__ unsigned sm[];
    unsigned* As0 = sm;
    unsigned* Ws0 = sm + 128 * GST;
    unsigned* As1 = sm + 2 * 128 * GST;
    unsigned* Ws1 = sm + 3 * 128 * GST;

    const int tid  = threadIdx.x;
    const int lane = tid & 31;
    const int wid  = tid >> 5;
    const int g    = lane >> 2;
    const int t    = lane & 3;
    const int wm = (wid & 3) * 32;
    const int wn = (wid >> 2) * 64;
    const int m0 = blockIdx.y * 128;
    const int n0 = blockIdx.x * 128;

    const float* Ab = A + (size_t)m0 * GK;
    const float* Wb = W + (size_t)n0 * GK;

    GEMM_MAINLOOP(Ab, Wb)

    #pragma unroll
    for (int mi = 0; mi < 2; mi++) {
        int r0 = m0 + wm + mi * 16 + g;
        #pragma unroll
        for (int j = 0; j < 8; j++) {
            int cc = n0 + wn + j * 8 + 2 * t;
            *(float2*)(C + (size_t)r0 * N + cc) =
                make_float2(acc[mi][j][0], acc[mi][j][1]);
            *(float2*)(C + (size_t)(r0 + 8) * N + cc) =
                make_float2(acc[mi][j][2], acc[mi][j][3]);
        }
    }
}

// ---------------------------------------------------------------------------
// Causal flash attention, tf32 mma.sync, online softmax.
// Q/K/P use k-permuted smem (LDS.64 fragments); V unchanged.
// Heavy tiles launch first (qb reversed).
// ---------------------------------------------------------------------------
#define FSQ 136     // Qs/Ks row stride (pair-bank 4g+t, conflict-free)
#define FSV 136     // Vs row stride (unpermuted, conflict-free scalar loads)
#define FSP 72      // Ps row stride (permuted)

__global__ __launch_bounds__(256) void flash_tf32(
    const float* __restrict__ Qt, const float* __restrict__ Kt,
    const float* __restrict__ Vlin, float* __restrict__ Y)
{
    extern __shared__ unsigned smu[];
    unsigned* Qs = smu;                    // 128 * 136
    unsigned* Ks = Qs + 128 * FSQ;         //  64 * 136
    unsigned* Vs = Ks + 64 * FSQ;          //  64 * 136
    unsigned* Ps = Vs + 64 * FSV;          // 128 * 72

    const int tid  = threadIdx.x;
    const int lane = tid & 31;
    const int wid  = tid >> 5;
    const int g    = lane >> 2;
    const int t    = lane & 3;
    const int qb = (gridDim.x - 1) - blockIdx.x;   // heavy-first
    const int q0 = qb * 128;
    const int bh = blockIdx.y;
    const int b  = bh / H_;
    const int h  = bh % H_;
    const int kvh = h / GROUPS_;
    const int wr  = wid * 16;

    // Ps write positions for permuted layout (perm(c) = 2*(c%4) + c/4)
    const int p0w = 2 * ((2 * t) & 3) + ((2 * t) >> 2);
    const int p1w = 2 * ((2 * t + 1) & 3) + ((2 * t + 1) >> 2);

    // ---- stage Q tile (128 rows x 16 k-groups), permuted ----
    {
        const float* qbase = Qt + ((size_t)bh * T_ + q0) * D_;
        #pragma unroll
        for (int l = 0; l < 8; l++) {
            int G  = tid + l * 256;          // 0..2047
            int r  = G >> 4;
            int c8 = (G & 15) * 8;
            float4 v0 = *(const float4*)(qbase + (size_t)r * D_ + c8);
            float4 v1 = *(const float4*)(qbase + (size_t)r * D_ + c8 + 4);
            unsigned* p = &Qs[r * FSQ + c8];
            *(uint2*)&p[0] = make_uint2(f2tf(v0.x), f2tf(v1.x));
            *(uint2*)&p[2] = make_uint2(f2tf(v0.y), f2tf(v1.y));
            *(uint2*)&p[4] = make_uint2(f2tf(v0.z), f2tf(v1.z));
            *(uint2*)&p[6] = make_uint2(f2tf(v0.w), f2tf(v1.w));
        }
    }

    float oacc[16][4];
    #pragma unroll
    for (int j = 0; j < 16; j++)
        #pragma unroll
        for (int c = 0; c < 4; c++) oacc[j][c] = 0.f;
    float mrow[2] = {-INFINITY, -INFINITY};
    float lrow[2] = {0.f, 0.f};

    const float* kbase = Kt + ((size_t)(b * KVH_ + kvh) * T_) * D_;
    const float* vbase = Vlin + ((size_t)b * T_) * (KVH_ * D_) + kvh * D_;

    const int nkt = qb * 2 + 2;
    for (int kt = 0; kt < nkt; kt++) {
        const int k0 = kt * 64;
        __syncthreads();
        // ---- stage K (permuted, 64 rows x 16 groups = 4/thread) ----
        #pragma unroll
        for (int l = 0; l < 4; l++) {
            int G  = tid + l * 256;          // 0..1023
            int r  = G >> 4;
            int c8 = (G & 15) * 8;
            float4 v0 = *(const float4*)(kbase + (size_t)(k0 + r) * D_ + c8);
            float4 v1 = *(const float4*)(kbase + (size_t)(k0 + r) * D_ + c8 + 4);
            unsigned* p = &Ks[r * FSQ + c8];
            *(uint2*)&p[0] = make_uint2(f2tf(v0.x), f2tf(v1.x));
            *(uint2*)&p[2] = make_uint2(f2tf(v0.y), f2tf(v1.y));
            *(uint2*)&p[4] = make_uint2(f2tf(v0.z), f2tf(v1.z));
            *(uint2*)&p[6] = make_uint2(f2tf(v0.w), f2tf(v1.w));
        }
        // ---- stage V (plain) ----
        #pragma unroll
        for (int l = 0; l < 8; l++) {
            int idx = tid + l * 256;
            int r  = idx >> 5;
            int c4 = (idx & 31) * 4;
            float4 vv = *(const float4*)(vbase + (size_t)(k0 + r) * (KVH_ * D_) + c4);
            unsigned* pv = &Vs[r * FSV + c4];
            pv[0] = f2tf(vv.x); pv[1] = f2tf(vv.y); pv[2] = f2tf(vv.z); pv[3] = f2tf(vv.w);
        }
        __syncthreads();

        // ---- S = Q . K^T ----
        float s[8][4];
        #pragma unroll
        for (int j = 0; j < 8; j++)
            #pragma unroll
            for (int c = 0; c < 4; c++) s[j][c] = 0.f;

        #pragma unroll
        for (int ks = 0; ks < 16; ks++) {
            const int ko = ks * 8 + 2 * t;
            unsigned qa[4];
            uint2 v0 = *(const uint2*)&Qs[(wr + g)     * FSQ + ko];
            uint2 v1 = *(const uint2*)&Qs[(wr + g + 8) * FSQ + ko];
            qa[0] = v0.x; qa[2] = v0.y;
            qa[1] = v1.x; qa[3] = v1.y;
            #pragma unroll
            for (int j = 0; j < 8; j++) {
                uint2 kv = *(const uint2*)&Ks[(j * 8 + g) * FSQ + ko];
                unsigned kb[2] = {kv.x, kv.y};
                mma8(s[j], qa, kb);
            }
        }

        if (kt >= nkt - 2) {
            int row0 = q0 + wr + g;
            int row1 = row0 + 8;
            #pragma unroll
            for (int j = 0; j < 8; j++) {
                int c0 = k0 + j * 8 + 2 * t;
                int c1 = c0 + 1;
                if (c0 > row0) s[j][0] = -1e30f;
                if (c1 > row0) s[j][1] = -1e30f;
                if (c0 > row1) s[j][2] = -1e30f;
                if (c1 > row1) s[j][3] = -1e30f;
            }
        }

        #pragma unroll
        for (int ri = 0; ri < 2; ri++) {
            const int i0 = ri * 2, i1 = ri * 2 + 1;
            float mx = -1e30f;
            #pragma unroll
            for (int j = 0; j < 8; j++)
                mx = fmaxf(mx, fmaxf(s[j][i0], s[j][i1]));
            mx = fmaxf(mx, __shfl_xor_sync(0xffffffffu, mx, 1));
            mx = fmaxf(mx, __shfl_xor_sync(0xffffffffu, mx, 2));
            float mnew = fmaxf(mrow[ri], mx);
            float alpha = __expf(mrow[ri] - mnew);
            float rs = 0.f;
            #pragma unroll
            for (int j = 0; j < 8; j++) {
                float p0 = __expf(s[j][i0] - mnew);
                float p1 = __expf(s[j][i1] - mnew);
                s[j][i0] = p0; s[j][i1] = p1;
                rs += p0 + p1;
            }
            rs += __shfl_xor_sync(0xffffffffu, rs, 1);
            rs += __shfl_xor_sync(0xffffffffu, rs, 2);
            lrow[ri] = lrow[ri] * alpha + rs;
            mrow[ri] = mnew;
            #pragma unroll
            for (int j = 0; j < 16; j++) {
                oacc[j][i0] *= alpha;
                oacc[j][i1] *= alpha;
            }
        }

        // ---- write P tile (permuted positions; rows warp-private) ----
        #pragma unroll
        for (int j = 0; j < 8; j++) {
            Ps[(wr + g)     * FSP + j * 8 + p0w] = f2tf(s[j][0]);
            Ps[(wr + g)     * FSP + j * 8 + p1w] = f2tf(s[j][1]);
            Ps[(wr + g + 8) * FSP + j * 8 + p0w] = f2tf(s[j][2]);
            Ps[(wr + g + 8) * FSP + j * 8 + p1w] = f2tf(s[j][3]);
        }
        __syncwarp();

        // ---- O += P . V ----
        #pragma unroll
        for (int ks = 0; ks < 8; ks++) {
            const int ko = ks * 8 + 2 * t;
            unsigned pa[4];
            uint2 v0 = *(const uint2*)&Ps[(wr + g)     * FSP + ko];
            uint2 v1 = *(const uint2*)&Ps[(wr + g + 8) * FSP + ko];
            pa[0] = v0.x; pa[2] = v0.y;
            pa[1] = v1.x; pa[3] = v1.y;
            #pragma unroll
            for (int j = 0; j < 16; j++) {
                unsigned vb[2];
                vb[0] = Vs[(ks * 8 + t)     * FSV + j * 8 + g];
                vb[1] = Vs[(ks * 8 + t + 4) * FSV + j * 8 + g];
                mma8(oacc[j], pa, vb);
            }
        }
    }

    const float il0 = 1.f / lrow[0];
    const float il1 = 1.f / lrow[1];
    float* y0 = Y + (((size_t)(b * T_ + q0 + wr + g)) * H_ + h) * D_;
    float* y1 = y0 + (size_t)8 * H_ * D_;
    #pragma unroll
    for (int j = 0; j < 16; j++) {
        int col = j * 8 + 2 * t;
        *(float2*)(y0 + col) = make_float2(oacc[j][0] * il0, oacc[j][1] * il0);
        *(float2*)(y1 + col) = make_float2(oacc[j][2] * il1, oacc[j][3] * il1);
    }
}

// ---------------------------------------------------------------------------
extern "C" void kernel_launch(void* const* d_in, const int* in_sizes, int n_in,
                              void* d_out, int out_size)
{
    const float* x    = (const float*)d_in[0];
    const float* cosb = (const float*)d_in[1];
    const float* sinb = (const float*)d_in[2];
    const float* Wq   = (const float*)d_in[3];
    const float* Wk   = (const float*)d_in[4];
    const float* Wv   = (const float*)d_in[5];
    const float* Wo   = (const float*)d_in[6];
    float* out = (float*)d_out;

    float *qt, *ktp, *vlin, *y;
    cudaGetSymbolAddress((void**)&qt,   g_qt);
    cudaGetSymbolAddress((void**)&ktp,  g_kt);
    cudaGetSymbolAddress((void**)&vlin, g_vlin);
    cudaGetSymbolAddress((void**)&y,    g_y);

    cudaFuncSetAttribute(qkv_gemm, cudaFuncAttributeMaxDynamicSharedMemorySize,
                         GEMM_SMEM);
    cudaFuncSetAttribute(out_gemm, cudaFuncAttributeMaxDynamicSharedMemorySize,
                         GEMM_SMEM);

    // Fused QKV projection + RoPE + RMSNorm + transpose
    qkv_gemm<<<dim3(24, 32), 256, GEMM_SMEM>>>(x, Wq, Wk, Wv, cosb, sinb,
                                               qt, ktp, vlin);

    // Flash attention (tf32 mma.sync, heavy-first)
    size_t fsmem = (size_t)(128 * FSQ + 64 * FSQ + 64 * FSV + 128 * FSP) * 4;
    cudaFuncSetAttribute(flash_tf32,
                         cudaFuncAttributeMaxDynamicSharedMemorySize, (int)fsmem);
    flash_tf32<<<dim3(T_ / 128, B_ * H_), 256, fsmem>>>(qt, ktp, vlin, y);

    // Output projection
    out_gemm<<<dim3(C_ / 128, 32), 256, GEMM_SMEM>>>(y, Wo, out, C_);
}

// round 6
// speedup vs baseline: 1.2059x; 1.2059x over previous
#include <cuda_runtime.h>
#include <math.h>
#include <stdint.h>

#define B_    2
#define T_    2048
#define C_    2048
#define H_    16
#define KVH_  4
#define D_    128
#define GROUPS_ (H_/KVH_)
#define EPS_  1.1920929e-07f

#define GK    2048          // K dim of all big GEMMs
#define NIT   64            // GK / 32

// ---------------- scratch (device globals; no cudaMalloc allowed) ----------
__device__ float g_xc  [B_*T_*C_];        // x  as tf32 bits
__device__ float g_wqc [H_*D_*C_];        // Wq as tf32 bits
__device__ float g_wkc [KVH_*D_*C_];      // Wk as tf32 bits
__device__ float g_wvc [KVH_*D_*C_];      // Wv as tf32 bits
__device__ float g_woc [C_*C_];           // Wo as tf32 bits
__device__ float g_qt  [B_*T_*H_*D_];     // [B,H,T,D]  rope+rms+scale (tf32 bits)
__device__ float g_kt  [B_*T_*KVH_*D_];   // [B,KVH,T,D] (tf32 bits)
__device__ float g_vlin[B_*T_*KVH_*D_];   // [B*T, KVH*D] (tf32 bits)
__device__ float g_y   [B_*T_*H_*D_];     // [B,T,H*D]  attention out (tf32 bits)

// ---------------------------------------------------------------------------
// helpers
// ---------------------------------------------------------------------------
__device__ __forceinline__ unsigned f2tf(float f) {
    unsigned u;
    asm("cvt.rna.tf32.f32 %0, %1;" : "=r"(u) : "f"(f));
    return u;
}
__device__ __forceinline__ float f2tf_f(float f) {
    return __uint_as_float(f2tf(f));
}

__device__ __forceinline__ uint32_t smem_u32(const void* p) {
    uint32_t a;
    asm("{ .reg .u64 t; cvta.to.shared.u64 t, %1; cvt.u32.u64 %0, t; }"
        : "=r"(a) : "l"(p));
    return a;
}

__device__ __forceinline__ void mma8(float* d, const unsigned* a, const unsigned* b) {
    asm volatile(
        "mma.sync.aligned.m16n8k8.row.col.f32.tf32.tf32.f32 "
        "{%0,%1,%2,%3}, {%4,%5,%6,%7}, {%8,%9}, {%0,%1,%2,%3};\n"
        : "+f"(d[0]), "+f"(d[1]), "+f"(d[2]), "+f"(d[3])
        : "r"(a[0]), "r"(a[1]), "r"(a[2]), "r"(a[3]), "r"(b[0]), "r"(b[1]));
}

#define CPC() asm volatile("cp.async.commit_group;" ::: "memory")
#define CPW1() asm volatile("cp.async.wait_group 1;" ::: "memory")

// ---------------------------------------------------------------------------
// tf32 pre-convert (elementwise, memory-bound)
// ---------------------------------------------------------------------------
__global__ __launch_bounds__(256) void cvt_tf32_kernel(
    const float4* __restrict__ in, float4* __restrict__ out, int n4)
{
    int i = blockIdx.x * 256 + threadIdx.x;
    if (i < n4) {
        float4 v = in[i];
        out[i] = make_float4(f2tf_f(v.x), f2tf_f(v.y), f2tf_f(v.z), f2tf_f(v.w));
    }
}

// ---------------------------------------------------------------------------
// GEMM machinery: 128x128 CTA tile, BK=32, 256 thr = 8 warps (4M x 2N),
// warp tile 32x64. Inputs are PRE-CONVERTED tf32 bits -> staging is pure
// cp.async (no LDG/cvt/STS). 3-stage ring, smem stride 36 (R4-proven
// conflict-free consumption with scalar LDS.32).
// ---------------------------------------------------------------------------
#define TILEW 4608                       // 128 * 36 words per matrix tile
#define TILEB (TILEW * 4)                // bytes
#define GEMM_SMEM (3 * 2 * TILEB)        // 110592 B

__device__ __forceinline__ void issue_tile(uint32_t sA, uint32_t sW,
                                           const float* Ab, const float* Wb,
                                           int k0, int tid)
{
    #pragma unroll
    for (int l = 0; l < 4; l++) {
        int idx = tid + l * 256;          // 0..1023 : 128 rows x 8 chunks
        int r  = idx >> 3;
        int c4 = (idx & 7) * 4;
        uint32_t off = (uint32_t)(r * 36 + c4) * 4;
        const float* a = Ab + (size_t)r * GK + k0 + c4;
        const float* w = Wb + (size_t)r * GK + k0 + c4;
        asm volatile(
            "cp.async.cg.shared.global [%0], [%1], 16;\n\t"
            "cp.async.cg.shared.global [%2], [%3], 16;"
            :: "r"(sA + off), "l"(a), "r"(sW + off), "l"(w));
    }
}

__device__ __forceinline__ void mma_tile(const unsigned* As, const unsigned* Ws,
                                         int wm, int wn, int g, int t,
                                         float acc[2][8][4]) {
    #pragma unroll
    for (int kk = 0; kk < 32; kk += 8) {
        unsigned a[2][4], b[8][2];
        #pragma unroll
        for (int mi = 0; mi < 2; mi++) {
            int r = wm + mi * 16;
            a[mi][0] = As[(r + g)     * 36 + kk + t];
            a[mi][1] = As[(r + g + 8) * 36 + kk + t];
            a[mi][2] = As[(r + g)     * 36 + kk + t + 4];
            a[mi][3] = As[(r + g + 8) * 36 + kk + t + 4];
        }
        #pragma unroll
        for (int j = 0; j < 8; j++) {
            b[j][0] = Ws[(wn + j * 8 + g) * 36 + kk + t];
            b[j][1] = Ws[(wn + j * 8 + g) * 36 + kk + t + 4];
        }
        #pragma unroll
        for (int mi = 0; mi < 2; mi++)
            #pragma unroll
            for (int j = 0; j < 8; j++)
                mma8(acc[mi][j], a[mi], b[j]);
    }
}

#define GEMM_MAINLOOP(Ab, Wb)                                                  \
    float acc[2][8][4];                                                        \
    _Pragma("unroll")                                                          \
    for (int mi = 0; mi < 2; mi++)                                             \
        _Pragma("unroll")                                                      \
        for (int j = 0; j < 8; j++)                                            \
            _Pragma("unroll")                                                  \
            for (int c = 0; c < 4; c++) acc[mi][j][c] = 0.f;                   \
    {                                                                          \
        const uint32_t sb0 = smem_u32(sm);                                     \
        issue_tile(sb0,             sb0 + TILEB,     Ab, Wb, 0,  tid); CPC();  \
        issue_tile(sb0 + 2 * TILEB, sb0 + 3 * TILEB, Ab, Wb, 32, tid); CPC();  \
        for (int it = 0; it < NIT; it++) {                                     \
            CPW1();                                                            \
            __syncthreads();                                                   \
            const int s = it - (it / 3) * 3;                                   \
            const unsigned* Ac = sm + s * 2 * TILEW;                           \
            const unsigned* Wc = Ac + TILEW;                                   \
            mma_tile(Ac, Wc, wm, wn, g, t, acc);                               \
            __syncthreads();                                                   \
            if (it + 2 < NIT) {                                                \
                const int sn = (it + 2) - ((it + 2) / 3) * 3;                  \
                issue_tile(sb0 + sn * 2 * TILEB, sb0 + (sn * 2 + 1) * TILEB,   \
                           Ab, Wb, (it + 2) * 32, tid);                        \
            }                                                                  \
            CPC();                                                             \
        }                                                                      \
    }

// ---------------------------------------------------------------------------
// Fused QKV projection + RoPE + RMSNorm epilogue (outputs tf32 bits).
// grid = (24, 32): nb<16 -> Q head nb; [16,20) -> K head; [20,24) -> V head.
// ---------------------------------------------------------------------------
__global__ __launch_bounds__(256, 2) void qkv_gemm(
    const float* __restrict__ x,
    const float* __restrict__ Wq, const float* __restrict__ Wk,
    const float* __restrict__ Wv,
    const float* __restrict__ cosb, const float* __restrict__ sinb,
    float* __restrict__ qt, float* __restrict__ kt, float* __restrict__ vlin)
{
    extern __shared__ unsigned sm[];

    const int tid  = threadIdx.x;
    const int lane = tid & 31;
    const int wid  = tid >> 5;
    const int g    = lane >> 2;
    const int t    = lane & 3;
    const int wm = (wid & 3) * 32;
    const int wn = (wid >> 2) * 64;
    const int m0 = blockIdx.y * 128;
    const int nb = blockIdx.x;

    const float* W;
    int nrow;
    if (nb < 16)      { W = Wq; nrow = nb * 128; }
    else if (nb < 20) { W = Wk; nrow = (nb - 16) * 128; }
    else              { W = Wv; nrow = (nb - 20) * 128; }
    const float* Ab = x + (size_t)m0 * GK;
    const float* Wb = W + (size_t)nrow * GK;

    GEMM_MAINLOOP(Ab, Wb)

    if (nb >= 20) {
        // ---- V: write tf32 bits to [B*T, KVH*D] ----
        const int n0 = (nb - 20) * 128;
        #pragma unroll
        for (int mi = 0; mi < 2; mi++) {
            int r0 = m0 + wm + mi * 16 + g;
            #pragma unroll
            for (int j = 0; j < 8; j++) {
                int cc = n0 + wn + j * 8 + 2 * t;
                *(float2*)(vlin + (size_t)r0 * (KVH_ * D_) + cc) =
                    make_float2(f2tf_f(acc[mi][j][0]), f2tf_f(acc[mi][j][1]));
                *(float2*)(vlin + (size_t)(r0 + 8) * (KVH_ * D_) + cc) =
                    make_float2(f2tf_f(acc[mi][j][2]), f2tf_f(acc[mi][j][3]));
            }
        }
        return;
    }

    // ---- Q/K: stage acc -> smem, then rope + rmsnorm + transpose ----
    float* St = (float*)sm;   // 128 rows x stride 132 = 67584 B <= GEMM_SMEM
    #pragma unroll
    for (int mi = 0; mi < 2; mi++) {
        int r0 = wm + mi * 16 + g;
        #pragma unroll
        for (int j = 0; j < 8; j++) {
            int cc = wn + j * 8 + 2 * t;
            St[r0 * 132 + cc]           = acc[mi][j][0];
            St[r0 * 132 + cc + 1]       = acc[mi][j][1];
            St[(r0 + 8) * 132 + cc]     = acc[mi][j][2];
            St[(r0 + 8) * 132 + cc + 1] = acc[mi][j][3];
        }
    }
    __syncthreads();

    {
        const int r  = tid >> 1;
        const int hf = tid & 1;
        const int m  = m0 + r;
        const int bb = m >> 11;
        const int tt = m & (T_ - 1);
        const float scale = (nb < 16) ? 0.08838834764831845f : 1.0f;

        const float* cr = cosb + tt * 64 + hf * 32;
        const float* sr = sinb + tt * 64 + hf * 32;
        const float* x1p = St + r * 132 + hf * 32;
        const float* x2p = x1p + 64;

        float o1[32], o2[32];
        float ss = 0.f;
        #pragma unroll
        for (int jj = 0; jj < 32; jj += 4) {
            float4 x1 = *(const float4*)(x1p + jj);
            float4 x2 = *(const float4*)(x2p + jj);
            float4 cv = *(const float4*)(cr + jj);
            float4 sv = *(const float4*)(sr + jj);
            float a0 = x1.x * cv.x + x2.x * sv.x, b0 = x2.x * cv.x - x1.x * sv.x;
            float a1 = x1.y * cv.y + x2.y * sv.y, b1 = x2.y * cv.y - x1.y * sv.y;
            float a2 = x1.z * cv.z + x2.z * sv.z, b2 = x2.z * cv.z - x1.z * sv.z;
            float a3 = x1.w * cv.w + x2.w * sv.w, b3 = x2.w * cv.w - x1.w * sv.w;
            o1[jj] = a0; o1[jj+1] = a1; o1[jj+2] = a2; o1[jj+3] = a3;
            o2[jj] = b0; o2[jj+1] = b1; o2[jj+2] = b2; o2[jj+3] = b3;
            ss += a0*a0 + b0*b0 + a1*a1 + b1*b1 + a2*a2 + b2*b2 + a3*a3 + b3*b3;
        }
        ss += __shfl_xor_sync(0xffffffffu, ss, 1);
        const float rr = rsqrtf(ss * (1.f / 128.f) + EPS_) * scale;

        float* ob;
        if (nb < 16)
            ob = qt + (((size_t)(bb * H_ + nb) * T_ + tt) * D_);
        else
            ob = kt + (((size_t)(bb * KVH_ + (nb - 16)) * T_ + tt) * D_);

        #pragma unroll
        for (int jj = 0; jj < 32; jj += 4) {
            *(float4*)(ob + hf * 32 + jj) = make_float4(
                f2tf_f(o1[jj] * rr), f2tf_f(o1[jj+1] * rr),
                f2tf_f(o1[jj+2] * rr), f2tf_f(o1[jj+3] * rr));
            *(float4*)(ob + 64 + hf * 32 + jj) = make_float4(
                f2tf_f(o2[jj] * rr), f2tf_f(o2[jj+1] * rr),
                f2tf_f(o2[jj+2] * rr), f2tf_f(o2[jj+3] * rr));
        }
    }
}

// ---------------------------------------------------------------------------
// Plain GEMM (output projection; inputs tf32 bits, output fp32)
// ---------------------------------------------------------------------------
__global__ __launch_bounds__(256, 2) void out_gemm(
    const float* __restrict__ A, const float* __restrict__ W,
    float* __restrict__ C, int N)
{
    extern __shared__ unsigned sm[];

    const int tid  = threadIdx.x;
    const int lane = tid & 31;
    const int wid  = tid >> 5;
    const int g    = lane >> 2;
    const int t    = lane & 3;
    const int wm = (wid & 3) * 32;
    const int wn = (wid >> 2) * 64;
    const int m0 = blockIdx.y * 128;
    const int n0 = blockIdx.x * 128;

    const float* Ab = A + (size_t)m0 * GK;
    const float* Wb = W + (size_t)n0 * GK;

    GEMM_MAINLOOP(Ab, Wb)

    #pragma unroll
    for (int mi = 0; mi < 2; mi++) {
        int r0 = m0 + wm + mi * 16 + g;
        #pragma unroll
        for (int j = 0; j < 8; j++) {
            int cc = n0 + wn + j * 8 + 2 * t;
            *(float2*)(C + (size_t)r0 * N + cc) =
                make_float2(acc[mi][j][0], acc[mi][j][1]);
            *(float2*)(C + (size_t)(r0 + 8) * N + cc) =
                make_float2(acc[mi][j][2], acc[mi][j][3]);
        }
    }
}

// ---------------------------------------------------------------------------
// Causal flash attention, tf32 mma.sync, online softmax.
// Inputs qt/kt/vlin are tf32 bits -> staging is plain copies (no cvt).
// Output y is tf32 bits (consumed by out_gemm). Heavy tiles first.
// ---------------------------------------------------------------------------
#define FSQ 132
#define FSV 136
#define FSP 68

__global__ __launch_bounds__(256) void flash_tf32(
    const float* __restrict__ Qt, const float* __restrict__ Kt,
    const float* __restrict__ Vlin, float* __restrict__ Y)
{
    extern __shared__ unsigned smu[];
    unsigned* Qs = smu;
    unsigned* Ks = Qs + 128 * FSQ;
    unsigned* Vs = Ks + 64 * FSQ;
    unsigned* Ps = Vs + 64 * FSV;

    const int tid  = threadIdx.x;
    const int lane = tid & 31;
    const int wid  = tid >> 5;
    const int g    = lane >> 2;
    const int t    = lane & 3;
    const int qb = (gridDim.x - 1) - blockIdx.x;   // heavy-first
    const int q0 = qb * 128;
    const int bh = blockIdx.y;
    const int b  = bh / H_;
    const int h  = bh % H_;
    const int kvh = h / GROUPS_;
    const int wr  = wid * 16;

    {
        const float* qbase = Qt + ((size_t)bh * T_ + q0) * D_;
        #pragma unroll
        for (int l = 0; l < 16; l++) {
            int idx = tid + l * 256;
            int r  = idx >> 5;
            int c4 = (idx & 31) * 4;
            *(uint4*)&Qs[r * FSQ + c4] = *(const uint4*)(qbase + (size_t)r * D_ + c4);
        }
    }

    float oacc[16][4];
    #pragma unroll
    for (int j = 0; j < 16; j++)
        #pragma unroll
        for (int c = 0; c < 4; c++) oacc[j][c] = 0.f;
    float mrow[2] = {-INFINITY, -INFINITY};
    float lrow[2] = {0.f, 0.f};

    const float* kbase = Kt + ((size_t)(b * KVH_ + kvh) * T_) * D_;
    const float* vbase = Vlin + ((size_t)b * T_) * (KVH_ * D_) + kvh * D_;

    const int nkt = qb * 2 + 2;
    for (int kt = 0; kt < nkt; kt++) {
        const int k0 = kt * 64;
        __syncthreads();
        #pragma unroll
        for (int l = 0; l < 8; l++) {
            int idx = tid + l * 256;
            int r  = idx >> 5;
            int c4 = (idx & 31) * 4;
            *(uint4*)&Ks[r * FSQ + c4] =
                *(const uint4*)(kbase + (size_t)(k0 + r) * D_ + c4);
            *(uint4*)&Vs[r * FSV + c4] =
                *(const uint4*)(vbase + (size_t)(k0 + r) * (KVH_ * D_) + c4);
        }
        __syncthreads();

        float s[8][4];
        #pragma unroll
        for (int j = 0; j < 8; j++)
            #pragma unroll
            for (int c = 0; c < 4; c++) s[j][c] = 0.f;

        #pragma unroll
        for (int ks = 0; ks < 16; ks++) {
            unsigned qa[4];
            qa[0] = Qs[(wr + g)     * FSQ + ks * 8 + t];
            qa[1] = Qs[(wr + g + 8) * FSQ + ks * 8 + t];
            qa[2] = Qs[(wr + g)     * FSQ + ks * 8 + t + 4];
            qa[3] = Qs[(wr + g + 8) * FSQ + ks * 8 + t + 4];
            #pragma unroll
            for (int j = 0; j < 8; j++) {
                unsigned kb[2];
                kb[0] = Ks[(j * 8 + g) * FSQ + ks * 8 + t];
                kb[1] = Ks[(j * 8 + g) * FSQ + ks * 8 + t + 4];
                mma8(s[j], qa, kb);
            }
        }

        if (kt >= nkt - 2) {
            int row0 = q0 + wr + g;
            int row1 = row0 + 8;
            #pragma unroll
            for (int j = 0; j < 8; j++) {
                int c0 = k0 + j * 8 + 2 * t;
                int c1 = c0 + 1;
                if (c0 > row0) s[j][0] = -1e30f;
                if (c1 > row0) s[j][1] = -1e30f;
                if (c0 > row1) s[j][2] = -1e30f;
                if (c1 > row1) s[j][3] = -1e30f;
            }
        }

        #pragma unroll
        for (int ri = 0; ri < 2; ri++) {
            const int i0 = ri * 2, i1 = ri * 2 + 1;
            float mx = -1e30f;
            #pragma unroll
            for (int j = 0; j < 8; j++)
                mx = fmaxf(mx, fmaxf(s[j][i0], s[j][i1]));
            mx = fmaxf(mx, __shfl_xor_sync(0xffffffffu, mx, 1));
            mx = fmaxf(mx, __shfl_xor_sync(0xffffffffu, mx, 2));
            float mnew = fmaxf(mrow[ri], mx);
            float alpha = __expf(mrow[ri] - mnew);
            float rs = 0.f;
            #pragma unroll
            for (int j = 0; j < 8; j++) {
                float p0 = __expf(s[j][i0] - mnew);
                float p1 = __expf(s[j][i1] - mnew);
                s[j][i0] = p0; s[j][i1] = p1;
                rs += p0 + p1;
            }
            rs += __shfl_xor_sync(0xffffffffu, rs, 1);
            rs += __shfl_xor_sync(0xffffffffu, rs, 2);
            lrow[ri] = lrow[ri] * alpha + rs;
            mrow[ri] = mnew;
            #pragma unroll
            for (int j = 0; j < 16; j++) {
                oacc[j][i0] *= alpha;
                oacc[j][i1] *= alpha;
            }
        }

        #pragma unroll
        for (int j = 0; j < 8; j++) {
            Ps[(wr + g)     * FSP + j * 8 + 2 * t]     = f2tf(s[j][0]);
            Ps[(wr + g)     * FSP + j * 8 + 2 * t + 1] = f2tf(s[j][1]);
            Ps[(wr + g + 8) * FSP + j * 8 + 2 * t]     = f2tf(s[j][2]);
            Ps[(wr + g + 8) * FSP + j * 8 + 2 * t + 1] = f2tf(s[j][3]);
        }
        __syncwarp();

        #pragma unroll
        for (int ks = 0; ks < 8; ks++) {
            unsigned pa[4];
            pa[0] = Ps[(wr + g)     * FSP + ks * 8 + t];
            pa[1] = Ps[(wr + g + 8) * FSP + ks * 8 + t];
            pa[2] = Ps[(wr + g)     * FSP + ks * 8 + t + 4];
            pa[3] = Ps[(wr + g + 8) * FSP + ks * 8 + t + 4];
            #pragma unroll
            for (int j = 0; j < 16; j++) {
                unsigned vb[2];
                vb[0] = Vs[(ks * 8 + t)     * FSV + j * 8 + g];
                vb[1] = Vs[(ks * 8 + t + 4) * FSV + j * 8 + g];
                mma8(oacc[j], pa, vb);
            }
        }
    }

    // epilogue: y as tf32 bits (consumed by out_gemm)
    const float il0 = 1.f / lrow[0];
    const float il1 = 1.f / lrow[1];
    float* y0 = Y + (((size_t)(b * T_ + q0 + wr + g)) * H_ + h) * D_;
    float* y1 = y0 + (size_t)8 * H_ * D_;
    #pragma unroll
    for (int j = 0; j < 16; j++) {
        int col = j * 8 + 2 * t;
        *(float2*)(y0 + col) = make_float2(f2tf_f(oacc[j][0] * il0),
                                           f2tf_f(oacc[j][1] * il0));
        *(float2*)(y1 + col) = make_float2(f2tf_f(oacc[j][2] * il1),
                                           f2tf_f(oacc[j][3] * il1));
    }
}

// ---------------------------------------------------------------------------
extern "C" void kernel_launch(void* const* d_in, const int* in_sizes, int n_in,
                              void* d_out, int out_size)
{
    const float* x    = (const float*)d_in[0];
    const float* cosb = (const float*)d_in[1];
    const float* sinb = (const float*)d_in[2];
    const float* Wq   = (const float*)d_in[3];
    const float* Wk   = (const float*)d_in[4];
    const float* Wv   = (const float*)d_in[5];
    const float* Wo   = (const float*)d_in[6];
    float* out = (float*)d_out;

    float *xc, *wqc, *wkc, *wvc, *woc, *qt, *ktp, *vlin, *y;
    cudaGetSymbolAddress((void**)&xc,   g_xc);
    cudaGetSymbolAddress((void**)&wqc,  g_wqc);
    cudaGetSymbolAddress((void**)&wkc,  g_wkc);
    cudaGetSymbolAddress((void**)&wvc,  g_wvc);
    cudaGetSymbolAddress((void**)&woc,  g_woc);
    cudaGetSymbolAddress((void**)&qt,   g_qt);
    cudaGetSymbolAddress((void**)&ktp,  g_kt);
    cudaGetSymbolAddress((void**)&vlin, g_vlin);
    cudaGetSymbolAddress((void**)&y,    g_y);

    // ---- pre-convert operands to tf32 bits (memory-bound) ----
    const int nx  = B_ * T_ * C_ / 4;        // 2,097,152
    const int nwq = H_ * D_ * C_ / 4;        // 1,048,576
    const int nwk = KVH_ * D_ * C_ / 4;      //   262,144
    cvt_tf32_kernel<<<nx  / 256, 256>>>((const float4*)x,  (float4*)xc,  nx);
    cvt_tf32_kernel<<<nwq / 256, 256>>>((const float4*)Wq, (float4*)wqc, nwq);
    cvt_tf32_kernel<<<nwk / 256, 256>>>((const float4*)Wk, (float4*)wkc, nwk);
    cvt_tf32_kernel<<<nwk / 256, 256>>>((const float4*)Wv, (float4*)wvc, nwk);
    cvt_tf32_kernel<<<nwq / 256, 256>>>((const float4*)Wo, (float4*)woc, nwq);

    cudaFuncSetAttribute(qkv_gemm, cudaFuncAttributeMaxDynamicSharedMemorySize,
                         GEMM_SMEM);
    cudaFuncSetAttribute(out_gemm, cudaFuncAttributeMaxDynamicSharedMemorySize,
                         GEMM_SMEM);

    // Fused QKV projection + RoPE + RMSNorm + transpose
    qkv_gemm<<<dim3(24, 32), 256, GEMM_SMEM>>>(xc, wqc, wkc, wvc, cosb, sinb,
                                               qt, ktp, vlin);

    // Flash attention (tf32 mma.sync, heavy-first)
    size_t fsmem = (size_t)(128 * FSQ + 64 * FSQ + 64 * FSV + 128 * FSP) * 4;
    cudaFuncSetAttribute(flash_tf32,
                         cudaFuncAttributeMaxDynamicSharedMemorySize, (int)fsmem);
    flash_tf32<<<dim3(T_ / 128, B_ * H_), 256, fsmem>>>(qt, ktp, vlin, y);

    // Output projection
    out_gemm<<<dim3(C_ / 128, 32), 256, GEMM_SMEM>>>(y, woc, out, C_);
}

// round 7
// speedup vs baseline: 1.3356x; 1.1075x over previous
#include <cuda_runtime.h>
#include <math.h>
#include <stdint.h>

#define B_    2
#define T_    2048
#define C_    2048
#define H_    16
#define KVH_  4
#define D_    128
#define GROUPS_ (H_/KVH_)
#define EPS_  1.1920929e-07f

#define GK    2048          // K dim of all big GEMMs
#define NIT   64            // GK / 32

// ---------------- scratch (device globals; no cudaMalloc allowed) ----------
__device__ float g_xc  [B_*T_*C_];        // x  as tf32 bits
__device__ float g_wqc [H_*D_*C_];        // Wq as tf32 bits
__device__ float g_wkc [KVH_*D_*C_];      // Wk as tf32 bits
__device__ float g_wvc [KVH_*D_*C_];      // Wv as tf32 bits
__device__ float g_woc [C_*C_];           // Wo as tf32 bits
__device__ float g_qt  [B_*T_*H_*D_];     // [B,H,T,D]  rope+rms+scale (tf32 bits)
__device__ float g_kt  [B_*T_*KVH_*D_];   // [B,KVH,T,D] (tf32 bits)
__device__ float g_vlin[B_*T_*KVH_*D_];   // [B*T, KVH*D] (tf32 bits)
__device__ float g_y   [B_*T_*H_*D_];     // [B,T,H*D]  attention out (tf32 bits)

// ---------------------------------------------------------------------------
// helpers
// ---------------------------------------------------------------------------
__device__ __forceinline__ unsigned f2tf(float f) {
    unsigned u;
    asm("cvt.rna.tf32.f32 %0, %1;" : "=r"(u) : "f"(f));
    return u;
}
__device__ __forceinline__ float f2tf_f(float f) {
    return __uint_as_float(f2tf(f));
}

__device__ __forceinline__ uint32_t smem_u32(const void* p) {
    uint32_t a;
    asm("{ .reg .u64 t; cvta.to.shared.u64 t, %1; cvt.u32.u64 %0, t; }"
        : "=r"(a) : "l"(p));
    return a;
}

__device__ __forceinline__ void mma8(float* d, const unsigned* a, const unsigned* b) {
    asm volatile(
        "mma.sync.aligned.m16n8k8.row.col.f32.tf32.tf32.f32 "
        "{%0,%1,%2,%3}, {%4,%5,%6,%7}, {%8,%9}, {%0,%1,%2,%3};\n"
        : "+f"(d[0]), "+f"(d[1]), "+f"(d[2]), "+f"(d[3])
        : "r"(a[0]), "r"(a[1]), "r"(a[2]), "r"(a[3]), "r"(b[0]), "r"(b[1]));
}

#define CPC() asm volatile("cp.async.commit_group;" ::: "memory")
#define CPW1() asm volatile("cp.async.wait_group 1;" ::: "memory")

// ---------------------------------------------------------------------------
// tf32 pre-convert (elementwise, memory-bound)
// ---------------------------------------------------------------------------
__global__ __launch_bounds__(256) void cvt_tf32_kernel(
    const float4* __restrict__ in, float4* __restrict__ out, int n4)
{
    int i = blockIdx.x * 256 + threadIdx.x;
    if (i < n4) {
        float4 v = in[i];
        out[i] = make_float4(f2tf_f(v.x), f2tf_f(v.y), f2tf_f(v.z), f2tf_f(v.w));
    }
}

// ---------------------------------------------------------------------------
// GEMM machinery: 256x128 CTA tile, BK=32, 256 thr = 8 warps (4M x 2N),
// warp tile 64x64 (mi=4, j=8) -> 128 B smem per MMA (vs 192 at 32x64).
// Inputs are pre-converted tf32 bits -> staging is pure cp.async.
// 3-stage ring, ONE barrier per iteration, smem stride 36 (conflict-free).
// ---------------------------------------------------------------------------
#define TAW (256 * 36)                  // A tile words
#define TWW (128 * 36)                  // W tile words
#define STGW (TAW + TWW)                // stage words  = 13824
#define STGB (STGW * 4)                 // stage bytes  = 55296
#define GEMM_SMEM (3 * STGB)            // 165888 B

__device__ __forceinline__ void issue_tile(uint32_t stg, const float* Ab,
                                           const float* Wb, int k0, int tid)
{
    #pragma unroll
    for (int l = 0; l < 8; l++) {
        int idx = tid + l * 256;          // 0..2047 : 256 rows x 8 chunks
        int r  = idx >> 3;
        int c4 = (idx & 7) * 4;
        asm volatile("cp.async.cg.shared.global [%0], [%1], 16;"
            :: "r"(stg + (uint32_t)(r * 36 + c4) * 4),
               "l"(Ab + (size_t)r * GK + k0 + c4));
    }
    #pragma unroll
    for (int l = 0; l < 4; l++) {
        int idx = tid + l * 256;          // 0..1023 : 128 rows x 8 chunks
        int r  = idx >> 3;
        int c4 = (idx & 7) * 4;
        asm volatile("cp.async.cg.shared.global [%0], [%1], 16;"
            :: "r"(stg + (uint32_t)(TAW + r * 36 + c4) * 4),
               "l"(Wb + (size_t)r * GK + k0 + c4));
    }
}

__device__ __forceinline__ void mma_tile(const unsigned* As, const unsigned* Ws,
                                         int wm, int wn, int g, int t,
                                         float acc[4][8][4]) {
    #pragma unroll
    for (int kk = 0; kk < 32; kk += 8) {
        unsigned a[4][4], b[8][2];
        #pragma unroll
        for (int mi = 0; mi < 4; mi++) {
            int r = wm + mi * 16;
            a[mi][0] = As[(r + g)     * 36 + kk + t];
            a[mi][1] = As[(r + g + 8) * 36 + kk + t];
            a[mi][2] = As[(r + g)     * 36 + kk + t + 4];
            a[mi][3] = As[(r + g + 8) * 36 + kk + t + 4];
        }
        #pragma unroll
        for (int j = 0; j < 8; j++) {
            b[j][0] = Ws[(wn + j * 8 + g) * 36 + kk + t];
            b[j][1] = Ws[(wn + j * 8 + g) * 36 + kk + t + 4];
        }
        #pragma unroll
        for (int mi = 0; mi < 4; mi++)
            #pragma unroll
            for (int j = 0; j < 8; j++)
                mma8(acc[mi][j], a[mi], b[j]);
    }
}

#define GEMM_MAINLOOP(Ab, Wb)                                                  \
    float acc[4][8][4];                                                        \
    _Pragma("unroll")                                                          \
    for (int mi = 0; mi < 4; mi++)                                             \
        _Pragma("unroll")                                                      \
        for (int j = 0; j < 8; j++)                                            \
            _Pragma("unroll")                                                  \
            for (int c = 0; c < 4; c++) acc[mi][j][c] = 0.f;                   \
    {                                                                          \
        const uint32_t sb0 = smem_u32(sm);                                     \
        issue_tile(sb0,        Ab, Wb, 0,  tid); CPC();                        \
        issue_tile(sb0 + STGB, Ab, Wb, 32, tid); CPC();                        \
        for (int it = 0; it < NIT; it++) {                                     \
            CPW1();                                                            \
            __syncthreads();                                                   \
            const int s = it - (it / 3) * 3;                                   \
            const unsigned* Ac = sm + s * STGW;                                \
            const unsigned* Wc = Ac + TAW;                                     \
            mma_tile(Ac, Wc, wm, wn, g, t, acc);                               \
            if (it + 2 < NIT) {                                                \
                const int sn = (it + 2) - ((it + 2) / 3) * 3;                  \
                issue_tile(sb0 + sn * STGB, Ab, Wb, (it + 2) * 32, tid);       \
            }                                                                  \
            CPC();                                                             \
        }                                                                      \
    }

// ---------------------------------------------------------------------------
// Fused QKV projection + RoPE + RMSNorm epilogue (outputs tf32 bits).
// grid = (24, 16): nb<16 -> Q head nb; [16,20) -> K head; [20,24) -> V head.
// ---------------------------------------------------------------------------
__global__ __launch_bounds__(256, 1) void qkv_gemm(
    const float* __restrict__ x,
    const float* __restrict__ Wq, const float* __restrict__ Wk,
    const float* __restrict__ Wv,
    const float* __restrict__ cosb, const float* __restrict__ sinb,
    float* __restrict__ qt, float* __restrict__ kt, float* __restrict__ vlin)
{
    extern __shared__ unsigned sm[];

    const int tid  = threadIdx.x;
    const int lane = tid & 31;
    const int wid  = tid >> 5;
    const int g    = lane >> 2;
    const int t    = lane & 3;
    const int wm = (wid & 3) * 64;
    const int wn = (wid >> 2) * 64;
    const int m0 = blockIdx.y * 256;
    const int nb = blockIdx.x;

    const float* W;
    if (nb < 16)      W = Wq + (size_t)nb * 128 * GK;
    else if (nb < 20) W = Wk + (size_t)(nb - 16) * 128 * GK;
    else              W = Wv + (size_t)(nb - 20) * 128 * GK;
    const float* Ab = x + (size_t)m0 * GK;
    const float* Wb = W;

    GEMM_MAINLOOP(Ab, Wb)

    if (nb >= 20) {
        // ---- V: write tf32 bits to [B*T, KVH*D] ----
        const int n0 = (nb - 20) * 128;
        #pragma unroll
        for (int mi = 0; mi < 4; mi++) {
            int r0 = m0 + wm + mi * 16 + g;
            #pragma unroll
            for (int j = 0; j < 8; j++) {
                int cc = n0 + wn + j * 8 + 2 * t;
                *(float2*)(vlin + (size_t)r0 * (KVH_ * D_) + cc) =
                    make_float2(f2tf_f(acc[mi][j][0]), f2tf_f(acc[mi][j][1]));
                *(float2*)(vlin + (size_t)(r0 + 8) * (KVH_ * D_) + cc) =
                    make_float2(f2tf_f(acc[mi][j][2]), f2tf_f(acc[mi][j][3]));
            }
        }
        return;
    }

    // ---- Q/K: stage acc -> smem, then rope + rmsnorm + transpose ----
    __syncthreads();                     // mainloop smem reads done
    float* St = (float*)sm;              // 256 rows x stride 132 = 135168 B
    #pragma unroll
    for (int mi = 0; mi < 4; mi++) {
        int r0 = wm + mi * 16 + g;
        #pragma unroll
        for (int j = 0; j < 8; j++) {
            int cc = wn + j * 8 + 2 * t;
            St[r0 * 132 + cc]           = acc[mi][j][0];
            St[r0 * 132 + cc + 1]       = acc[mi][j][1];
            St[(r0 + 8) * 132 + cc]     = acc[mi][j][2];
            St[(r0 + 8) * 132 + cc + 1] = acc[mi][j][3];
        }
    }
    __syncthreads();

    const float scale = (nb < 16) ? 0.08838834764831845f : 1.0f;
    #pragma unroll
    for (int round = 0; round < 2; round++) {
        const int r  = (tid >> 1) + round * 128;
        const int hf = tid & 1;
        const int m  = m0 + r;
        const int bb = m >> 11;
        const int tt = m & (T_ - 1);

        const float* cr = cosb + tt * 64 + hf * 32;
        const float* sr = sinb + tt * 64 + hf * 32;
        const float* x1p = St + r * 132 + hf * 32;
        const float* x2p = x1p + 64;

        float o1[32], o2[32];
        float ss = 0.f;
        #pragma unroll
        for (int jj = 0; jj < 32; jj += 4) {
            float4 x1 = *(const float4*)(x1p + jj);
            float4 x2 = *(const float4*)(x2p + jj);
            float4 cv = *(const float4*)(cr + jj);
            float4 sv = *(const float4*)(sr + jj);
            float a0 = x1.x * cv.x + x2.x * sv.x, b0 = x2.x * cv.x - x1.x * sv.x;
            float a1 = x1.y * cv.y + x2.y * sv.y, b1 = x2.y * cv.y - x1.y * sv.y;
            float a2 = x1.z * cv.z + x2.z * sv.z, b2 = x2.z * cv.z - x1.z * sv.z;
            float a3 = x1.w * cv.w + x2.w * sv.w, b3 = x2.w * cv.w - x1.w * sv.w;
            o1[jj] = a0; o1[jj+1] = a1; o1[jj+2] = a2; o1[jj+3] = a3;
            o2[jj] = b0; o2[jj+1] = b1; o2[jj+2] = b2; o2[jj+3] = b3;
            ss += a0*a0 + b0*b0 + a1*a1 + b1*b1 + a2*a2 + b2*b2 + a3*a3 + b3*b3;
        }
        ss += __shfl_xor_sync(0xffffffffu, ss, 1);
        const float rr = rsqrtf(ss * (1.f / 128.f) + EPS_) * scale;

        float* ob;
        if (nb < 16)
            ob = qt + (((size_t)(bb * H_ + nb) * T_ + tt) * D_);
        else
            ob = kt + (((size_t)(bb * KVH_ + (nb - 16)) * T_ + tt) * D_);

        #pragma unroll
        for (int jj = 0; jj < 32; jj += 4) {
            *(float4*)(ob + hf * 32 + jj) = make_float4(
                f2tf_f(o1[jj] * rr), f2tf_f(o1[jj+1] * rr),
                f2tf_f(o1[jj+2] * rr), f2tf_f(o1[jj+3] * rr));
            *(float4*)(ob + 64 + hf * 32 + jj) = make_float4(
                f2tf_f(o2[jj] * rr), f2tf_f(o2[jj+1] * rr),
                f2tf_f(o2[jj+2] * rr), f2tf_f(o2[jj+3] * rr));
        }
    }
}

// ---------------------------------------------------------------------------
// Plain GEMM (output projection; inputs tf32 bits, output fp32)
// grid = (16, 16)
// ---------------------------------------------------------------------------
__global__ __launch_bounds__(256, 1) void out_gemm(
    const float* __restrict__ A, const float* __restrict__ W,
    float* __restrict__ C, int N)
{
    extern __shared__ unsigned sm[];

    const int tid  = threadIdx.x;
    const int lane = tid & 31;
    const int wid  = tid >> 5;
    const int g    = lane >> 2;
    const int t    = lane & 3;
    const int wm = (wid & 3) * 64;
    const int wn = (wid >> 2) * 64;
    const int m0 = blockIdx.y * 256;
    const int n0 = blockIdx.x * 128;

    const float* Ab = A + (size_t)m0 * GK;
    const float* Wb = W + (size_t)n0 * GK;

    GEMM_MAINLOOP(Ab, Wb)

    #pragma unroll
    for (int mi = 0; mi < 4; mi++) {
        int r0 = m0 + wm + mi * 16 + g;
        #pragma unroll
        for (int j = 0; j < 8; j++) {
            int cc = n0 + wn + j * 8 + 2 * t;
            *(float2*)(C + (size_t)r0 * N + cc) =
                make_float2(acc[mi][j][0], acc[mi][j][1]);
            *(float2*)(C + (size_t)(r0 + 8) * N + cc) =
                make_float2(acc[mi][j][2], acc[mi][j][3]);
        }
    }
}

// ---------------------------------------------------------------------------
// Causal flash attention, tf32 mma.sync, online softmax. (proven; unchanged)
// ---------------------------------------------------------------------------
#define FSQ 132
#define FSV 136
#define FSP 68

__global__ __launch_bounds__(256) void flash_tf32(
    const float* __restrict__ Qt, const float* __restrict__ Kt,
    const float* __restrict__ Vlin, float* __restrict__ Y)
{
    extern __shared__ unsigned smu[];
    unsigned* Qs = smu;
    unsigned* Ks = Qs + 128 * FSQ;
    unsigned* Vs = Ks + 64 * FSQ;
    unsigned* Ps = Vs + 64 * FSV;

    const int tid  = threadIdx.x;
    const int lane = tid & 31;
    const int wid  = tid >> 5;
    const int g    = lane >> 2;
    const int t    = lane & 3;
    const int qb = (gridDim.x - 1) - blockIdx.x;   // heavy-first
    const int q0 = qb * 128;
    const int bh = blockIdx.y;
    const int b  = bh / H_;
    const int h  = bh % H_;
    const int kvh = h / GROUPS_;
    const int wr  = wid * 16;

    {
        const float* qbase = Qt + ((size_t)bh * T_ + q0) * D_;
        #pragma unroll
        for (int l = 0; l < 16; l++) {
            int idx = tid + l * 256;
            int r  = idx >> 5;
            int c4 = (idx & 31) * 4;
            *(uint4*)&Qs[r * FSQ + c4] = *(const uint4*)(qbase + (size_t)r * D_ + c4);
        }
    }

    float oacc[16][4];
    #pragma unroll
    for (int j = 0; j < 16; j++)
        #pragma unroll
        for (int c = 0; c < 4; c++) oacc[j][c] = 0.f;
    float mrow[2] = {-INFINITY, -INFINITY};
    float lrow[2] = {0.f, 0.f};

    const float* kbase = Kt + ((size_t)(b * KVH_ + kvh) * T_) * D_;
    const float* vbase = Vlin + ((size_t)b * T_) * (KVH_ * D_) + kvh * D_;

    const int nkt = qb * 2 + 2;
    for (int kt = 0; kt < nkt; kt++) {
        const int k0 = kt * 64;
        __syncthreads();
        #pragma unroll
        for (int l = 0; l < 8; l++) {
            int idx = tid + l * 256;
            int r  = idx >> 5;
            int c4 = (idx & 31) * 4;
            *(uint4*)&Ks[r * FSQ + c4] =
                *(const uint4*)(kbase + (size_t)(k0 + r) * D_ + c4);
            *(uint4*)&Vs[r * FSV + c4] =
                *(const uint4*)(vbase + (size_t)(k0 + r) * (KVH_ * D_) + c4);
        }
        __syncthreads();

        float s[8][4];
        #pragma unroll
        for (int j = 0; j < 8; j++)
            #pragma unroll
            for (int c = 0; c < 4; c++) s[j][c] = 0.f;

        #pragma unroll
        for (int ks = 0; ks < 16; ks++) {
            unsigned qa[4];
            qa[0] = Qs[(wr + g)     * FSQ + ks * 8 + t];
            qa[1] = Qs[(wr + g + 8) * FSQ + ks * 8 + t];
            qa[2] = Qs[(wr + g)     * FSQ + ks * 8 + t + 4];
            qa[3] = Qs[(wr + g + 8) * FSQ + ks * 8 + t + 4];
            #pragma unroll
            for (int j = 0; j < 8; j++) {
                unsigned kb[2];
                kb[0] = Ks[(j * 8 + g) * FSQ + ks * 8 + t];
                kb[1] = Ks[(j * 8 + g) * FSQ + ks * 8 + t + 4];
                mma8(s[j], qa, kb);
            }
        }

        if (kt >= nkt - 2) {
            int row0 = q0 + wr + g;
            int row1 = row0 + 8;
            #pragma unroll
            for (int j = 0; j < 8; j++) {
                int c0 = k0 + j * 8 + 2 * t;
                int c1 = c0 + 1;
                if (c0 > row0) s[j][0] = -1e30f;
                if (c1 > row0) s[j][1] = -1e30f;
                if (c0 > row1) s[j][2] = -1e30f;
                if (c1 > row1) s[j][3] = -1e30f;
            }
        }

        #pragma unroll
        for (int ri = 0; ri < 2; ri++) {
            const int i0 = ri * 2, i1 = ri * 2 + 1;
            float mx = -1e30f;
            #pragma unroll
            for (int j = 0; j < 8; j++)
                mx = fmaxf(mx, fmaxf(s[j][i0], s[j][i1]));
            mx = fmaxf(mx, __shfl_xor_sync(0xffffffffu, mx, 1));
            mx = fmaxf(mx, __shfl_xor_sync(0xffffffffu, mx, 2));
            float mnew = fmaxf(mrow[ri], mx);
            float alpha = __expf(mrow[ri] - mnew);
            float rs = 0.f;
            #pragma unroll
            for (int j = 0; j < 8; j++) {
                float p0 = __expf(s[j][i0] - mnew);
                float p1 = __expf(s[j][i1] - mnew);
                s[j][i0] = p0; s[j][i1] = p1;
                rs += p0 + p1;
            }
            rs += __shfl_xor_sync(0xffffffffu, rs, 1);
            rs += __shfl_xor_sync(0xffffffffu, rs, 2);
            lrow[ri] = lrow[ri] * alpha + rs;
            mrow[ri] = mnew;
            #pragma unroll
            for (int j = 0; j < 16; j++) {
                oacc[j][i0] *= alpha;
                oacc[j][i1] *= alpha;
            }
        }

        #pragma unroll
        for (int j = 0; j < 8; j++) {
            Ps[(wr + g)     * FSP + j * 8 + 2 * t]     = f2tf(s[j][0]);
            Ps[(wr + g)     * FSP + j * 8 + 2 * t + 1] = f2tf(s[j][1]);
            Ps[(wr + g + 8) * FSP + j * 8 + 2 * t]     = f2tf(s[j][2]);
            Ps[(wr + g + 8) * FSP + j * 8 + 2 * t + 1] = f2tf(s[j][3]);
        }
        __syncwarp();

        #pragma unroll
        for (int ks = 0; ks < 8; ks++) {
            unsigned pa[4];
            pa[0] = Ps[(wr + g)     * FSP + ks * 8 + t];
            pa[1] = Ps[(wr + g + 8) * FSP + ks * 8 + t];
            pa[2] = Ps[(wr + g)     * FSP + ks * 8 + t + 4];
            pa[3] = Ps[(wr + g + 8) * FSP + ks * 8 + t + 4];
            #pragma unroll
            for (int j = 0; j < 16; j++) {
                unsigned vb[2];
                vb[0] = Vs[(ks * 8 + t)     * FSV + j * 8 + g];
                vb[1] = Vs[(ks * 8 + t + 4) * FSV + j * 8 + g];
                mma8(oacc[j], pa, vb);
            }
        }
    }

    const float il0 = 1.f / lrow[0];
    const float il1 = 1.f / lrow[1];
    float* y0 = Y + (((size_t)(b * T_ + q0 + wr + g)) * H_ + h) * D_;
    float* y1 = y0 + (size_t)8 * H_ * D_;
    #pragma unroll
    for (int j = 0; j < 16; j++) {
        int col = j * 8 + 2 * t;
        *(float2*)(y0 + col) = make_float2(f2tf_f(oacc[j][0] * il0),
                                           f2tf_f(oacc[j][1] * il0));
        *(float2*)(y1 + col) = make_float2(f2tf_f(oacc[j][2] * il1),
                                           f2tf_f(oacc[j][3] * il1));
    }
}

// ---------------------------------------------------------------------------
extern "C" void kernel_launch(void* const* d_in, const int* in_sizes, int n_in,
                              void* d_out, int out_size)
{
    const float* x    = (const float*)d_in[0];
    const float* cosb = (const float*)d_in[1];
    const float* sinb = (const float*)d_in[2];
    const float* Wq   = (const float*)d_in[3];
    const float* Wk   = (const float*)d_in[4];
    const float* Wv   = (const float*)d_in[5];
    const float* Wo   = (const float*)d_in[6];
    float* out = (float*)d_out;

    float *xc, *wqc, *wkc, *wvc, *woc, *qt, *ktp, *vlin, *y;
    cudaGetSymbolAddress((void**)&xc,   g_xc);
    cudaGetSymbolAddress((void**)&wqc,  g_wqc);
    cudaGetSymbolAddress((void**)&wkc,  g_wkc);
    cudaGetSymbolAddress((void**)&wvc,  g_wvc);
    cudaGetSymbolAddress((void**)&woc,  g_woc);
    cudaGetSymbolAddress((void**)&qt,   g_qt);
    cudaGetSymbolAddress((void**)&ktp,  g_kt);
    cudaGetSymbolAddress((void**)&vlin, g_vlin);
    cudaGetSymbolAddress((void**)&y,    g_y);

    // ---- pre-convert operands to tf32 bits (memory-bound) ----
    const int nx  = B_ * T_ * C_ / 4;
    const int nwq = H_ * D_ * C_ / 4;
    const int nwk = KVH_ * D_ * C_ / 4;
    cvt_tf32_kernel<<<nx  / 256, 256>>>((const float4*)x,  (float4*)xc,  nx);
    cvt_tf32_kernel<<<nwq / 256, 256>>>((const float4*)Wq, (float4*)wqc, nwq);
    cvt_tf32_kernel<<<nwk / 256, 256>>>((const float4*)Wk, (float4*)wkc, nwk);
    cvt_tf32_kernel<<<nwk / 256, 256>>>((const float4*)Wv, (float4*)wvc, nwk);
    cvt_tf32_kernel<<<nwq / 256, 256>>>((const float4*)Wo, (float4*)woc, nwq);

    cudaFuncSetAttribute(qkv_gemm, cudaFuncAttributeMaxDynamicSharedMemorySize,
                         GEMM_SMEM);
    cudaFuncSetAttribute(out_gemm, cudaFuncAttributeMaxDynamicSharedMemorySize,
                         GEMM_SMEM);

    // Fused QKV projection + RoPE + RMSNorm + transpose
    qkv_gemm<<<dim3(24, 16), 256, GEMM_SMEM>>>(xc, wqc, wkc, wvc, cosb, sinb,
                                               qt, ktp, vlin);

    // Flash attention (tf32 mma.sync, heavy-first)
    size_t fsmem = (size_t)(128 * FSQ + 64 * FSQ + 64 * FSV + 128 * FSP) * 4;
    cudaFuncSetAttribute(flash_tf32,
                         cudaFuncAttributeMaxDynamicSharedMemorySize, (int)fsmem);
    flash_tf32<<<dim3(T_ / 128, B_ * H_), 256, fsmem>>>(qt, ktp, vlin, y);

    // Output projection
    out_gemm<<<dim3(16, 16), 256, GEMM_SMEM>>>(y, woc, out, C_);
}

// round 8
// speedup vs baseline: 1.3857x; 1.0375x over previous
#include <cuda_runtime.h>
#include <math.h>
#include <stdint.h>

#define B_    2
#define T_    2048
#define C_    2048
#define H_    16
#define KVH_  4
#define D_    128
#define GROUPS_ (H_/KVH_)
#define EPS_  1.1920929e-07f

#define GK    2048          // K dim of all big GEMMs
#define NIT   64            // GK / 32

// ---------------- scratch (device globals; no cudaMalloc allowed) ----------
__device__ float g_xc  [B_*T_*C_];        // x  as tf32 bits
__device__ float g_wqc [H_*D_*C_];        // Wq as tf32 bits
__device__ float g_wkc [KVH_*D_*C_];      // Wk as tf32 bits
__device__ float g_wvc [KVH_*D_*C_];      // Wv as tf32 bits
__device__ float g_woc [C_*C_];           // Wo as tf32 bits
__device__ float g_qt  [B_*T_*H_*D_];     // [B,H,T,D]  rope+rms+scale (tf32 bits)
__device__ float g_kt  [B_*T_*KVH_*D_];   // [B,KVH,T,D] (tf32 bits)
__device__ float g_vlin[B_*T_*KVH_*D_];   // [B*T, KVH*D] (tf32 bits)
__device__ float g_y   [B_*T_*H_*D_];     // [B,T,H*D]  attention out (tf32 bits)

// ---------------------------------------------------------------------------
// helpers
// ---------------------------------------------------------------------------
__device__ __forceinline__ unsigned f2tf(float f) {
    unsigned u;
    asm("cvt.rna.tf32.f32 %0, %1;" : "=r"(u) : "f"(f));
    return u;
}
__device__ __forceinline__ float f2tf_f(float f) {
    return __uint_as_float(f2tf(f));
}

__device__ __forceinline__ uint32_t smem_u32(const void* p) {
    uint32_t a;
    asm("{ .reg .u64 t; cvta.to.shared.u64 t, %1; cvt.u32.u64 %0, t; }"
        : "=r"(a) : "l"(p));
    return a;
}

__device__ __forceinline__ void mma8(float* d, const unsigned* a, const unsigned* b) {
    asm volatile(
        "mma.sync.aligned.m16n8k8.row.col.f32.tf32.tf32.f32 "
        "{%0,%1,%2,%3}, {%4,%5,%6,%7}, {%8,%9}, {%0,%1,%2,%3};\n"
        : "+f"(d[0]), "+f"(d[1]), "+f"(d[2]), "+f"(d[3])
        : "r"(a[0]), "r"(a[1]), "r"(a[2]), "r"(a[3]), "r"(b[0]), "r"(b[1]));
}

#define CPC()  asm volatile("cp.async.commit_group;" ::: "memory")
#define CPW1() asm volatile("cp.async.wait_group 1;" ::: "memory")

// ---------------------------------------------------------------------------
// Fused tf32 pre-convert of all five operand tensors (one launch)
// ---------------------------------------------------------------------------
#define NX4  (B_*T_*C_/4)
#define NWQ4 (H_*D_*C_/4)
#define NWK4 (KVH_*D_*C_/4)
#define NCVT (NX4 + 2*NWQ4 + 2*NWK4)

__global__ __launch_bounds__(256) void cvt_all_kernel(
    const float4* __restrict__ x,  float4* __restrict__ xc,
    const float4* __restrict__ wq, float4* __restrict__ wqc,
    const float4* __restrict__ wk, float4* __restrict__ wkc,
    const float4* __restrict__ wv, float4* __restrict__ wvc,
    const float4* __restrict__ wo, float4* __restrict__ woc)
{
    int i = blockIdx.x * 256 + threadIdx.x;
    const float4* src; float4* dst; int off;
    if (i < NX4)                         { src = x;  dst = xc;  off = 0; }
    else if (i < NX4 + NWQ4)             { src = wq; dst = wqc; off = NX4; }
    else if (i < NX4 + NWQ4 + NWK4)      { src = wk; dst = wkc; off = NX4 + NWQ4; }
    else if (i < NX4 + NWQ4 + 2*NWK4)    { src = wv; dst = wvc; off = NX4 + NWQ4 + NWK4; }
    else                                 { src = wo; dst = woc; off = NX4 + NWQ4 + 2*NWK4; }
    int j = i - off;
    float4 v = src[j];
    dst[j] = make_float4(f2tf_f(v.x), f2tf_f(v.y), f2tf_f(v.z), f2tf_f(v.w));
}

// ---------------------------------------------------------------------------
// GEMM machinery (R7-proven): 256x128 CTA tile, BK=32, 8 warps (4M x 2N),
// warp tile 64x64, cp.async 3-stage ring, one barrier/iter, stride 36.
// ---------------------------------------------------------------------------
#define TAW (256 * 36)
#define TWW (128 * 36)
#define STGW (TAW + TWW)
#define STGB (STGW * 4)
#define GEMM_SMEM (3 * STGB)            // 165888 B

__device__ __forceinline__ void issue_tile(uint32_t stg, const float* Ab,
                                           const float* Wb, int k0, int tid)
{
    #pragma unroll
    for (int l = 0; l < 8; l++) {
        int idx = tid + l * 256;
        int r  = idx >> 3;
        int c4 = (idx & 7) * 4;
        asm volatile("cp.async.cg.shared.global [%0], [%1], 16;"
            :: "r"(stg + (uint32_t)(r * 36 + c4) * 4),
               "l"(Ab + (size_t)r * GK + k0 + c4));
    }
    #pragma unroll
    for (int l = 0; l < 4; l++) {
        int idx = tid + l * 256;
        int r  = idx >> 3;
        int c4 = (idx & 7) * 4;
        asm volatile("cp.async.cg.shared.global [%0], [%1], 16;"
            :: "r"(stg + (uint32_t)(TAW + r * 36 + c4) * 4),
               "l"(Wb + (size_t)r * GK + k0 + c4));
    }
}

__device__ __forceinline__ void mma_tile(const unsigned* As, const unsigned* Ws,
                                         int wm, int wn, int g, int t,
                                         float acc[4][8][4]) {
    #pragma unroll
    for (int kk = 0; kk < 32; kk += 8) {
        unsigned a[4][4], b[8][2];
        #pragma unroll
        for (int mi = 0; mi < 4; mi++) {
            int r = wm + mi * 16;
            a[mi][0] = As[(r + g)     * 36 + kk + t];
            a[mi][1] = As[(r + g + 8) * 36 + kk + t];
            a[mi][2] = As[(r + g)     * 36 + kk + t + 4];
            a[mi][3] = As[(r + g + 8) * 36 + kk + t + 4];
        }
        #pragma unroll
        for (int j = 0; j < 8; j++) {
            b[j][0] = Ws[(wn + j * 8 + g) * 36 + kk + t];
            b[j][1] = Ws[(wn + j * 8 + g) * 36 + kk + t + 4];
        }
        #pragma unroll
        for (int mi = 0; mi < 4; mi++)
            #pragma unroll
            for (int j = 0; j < 8; j++)
                mma8(acc[mi][j], a[mi], b[j]);
    }
}

#define GEMM_MAINLOOP(Ab, Wb)                                                  \
    float acc[4][8][4];                                                        \
    _Pragma("unroll")                                                          \
    for (int mi = 0; mi < 4; mi++)                                             \
        _Pragma("unroll")                                                      \
        for (int j = 0; j < 8; j++)                                            \
            _Pragma("unroll")                                                  \
            for (int c = 0; c < 4; c++) acc[mi][j][c] = 0.f;                   \
    {                                                                          \
        const uint32_t sb0 = smem_u32(sm);                                     \
        issue_tile(sb0,        Ab, Wb, 0,  tid); CPC();                        \
        issue_tile(sb0 + STGB, Ab, Wb, 32, tid); CPC();                        \
        for (int it = 0; it < NIT; it++) {                                     \
            CPW1();                                                            \
            __syncthreads();                                                   \
            const int s = it - (it / 3) * 3;                                   \
            const unsigned* Ac = sm + s * STGW;                                \
            const unsigned* Wc = Ac + TAW;                                     \
            mma_tile(Ac, Wc, wm, wn, g, t, acc);                               \
            if (it + 2 < NIT) {                                                \
                const int sn = (it + 2) - ((it + 2) / 3) * 3;                  \
                issue_tile(sb0 + sn * STGB, Ab, Wb, (it + 2) * 32, tid);       \
            }                                                                  \
            CPC();                                                             \
        }                                                                      \
    }

// ---------------------------------------------------------------------------
// Fused QKV projection + RoPE + RMSNorm epilogue (outputs tf32 bits).
// grid = (24, 16)
// ---------------------------------------------------------------------------
__global__ __launch_bounds__(256, 1) void qkv_gemm(
    const float* __restrict__ x,
    const float* __restrict__ Wq, const float* __restrict__ Wk,
    const float* __restrict__ Wv,
    const float* __restrict__ cosb, const float* __restrict__ sinb,
    float* __restrict__ qt, float* __restrict__ kt, float* __restrict__ vlin)
{
    extern __shared__ unsigned sm[];

    const int tid  = threadIdx.x;
    const int lane = tid & 31;
    const int wid  = tid >> 5;
    const int g    = lane >> 2;
    const int t    = lane & 3;
    const int wm = (wid & 3) * 64;
    const int wn = (wid >> 2) * 64;
    const int m0 = blockIdx.y * 256;
    const int nb = blockIdx.x;

    const float* W;
    if (nb < 16)      W = Wq + (size_t)nb * 128 * GK;
    else if (nb < 20) W = Wk + (size_t)(nb - 16) * 128 * GK;
    else              W = Wv + (size_t)(nb - 20) * 128 * GK;
    const float* Ab = x + (size_t)m0 * GK;
    const float* Wb = W;

    GEMM_MAINLOOP(Ab, Wb)

    if (nb >= 20) {
        const int n0 = (nb - 20) * 128;
        #pragma unroll
        for (int mi = 0; mi < 4; mi++) {
            int r0 = m0 + wm + mi * 16 + g;
            #pragma unroll
            for (int j = 0; j < 8; j++) {
                int cc = n0 + wn + j * 8 + 2 * t;
                *(float2*)(vlin + (size_t)r0 * (KVH_ * D_) + cc) =
                    make_float2(f2tf_f(acc[mi][j][0]), f2tf_f(acc[mi][j][1]));
                *(float2*)(vlin + (size_t)(r0 + 8) * (KVH_ * D_) + cc) =
                    make_float2(f2tf_f(acc[mi][j][2]), f2tf_f(acc[mi][j][3]));
            }
        }
        return;
    }

    __syncthreads();
    float* St = (float*)sm;
    #pragma unroll
    for (int mi = 0; mi < 4; mi++) {
        int r0 = wm + mi * 16 + g;
        #pragma unroll
        for (int j = 0; j < 8; j++) {
            int cc = wn + j * 8 + 2 * t;
            St[r0 * 132 + cc]           = acc[mi][j][0];
            St[r0 * 132 + cc + 1]       = acc[mi][j][1];
            St[(r0 + 8) * 132 + cc]     = acc[mi][j][2];
            St[(r0 + 8) * 132 + cc + 1] = acc[mi][j][3];
        }
    }
    __syncthreads();

    const float scale = (nb < 16) ? 0.08838834764831845f : 1.0f;
    #pragma unroll
    for (int round = 0; round < 2; round++) {
        const int r  = (tid >> 1) + round * 128;
        const int hf = tid & 1;
        const int m  = m0 + r;
        const int bb = m >> 11;
        const int tt = m & (T_ - 1);

        const float* cr = cosb + tt * 64 + hf * 32;
        const float* sr = sinb + tt * 64 + hf * 32;
        const float* x1p = St + r * 132 + hf * 32;
        const float* x2p = x1p + 64;

        float o1[32], o2[32];
        float ss = 0.f;
        #pragma unroll
        for (int jj = 0; jj < 32; jj += 4) {
            float4 x1 = *(const float4*)(x1p + jj);
            float4 x2 = *(const float4*)(x2p + jj);
            float4 cv = *(const float4*)(cr + jj);
            float4 sv = *(const float4*)(sr + jj);
            float a0 = x1.x * cv.x + x2.x * sv.x, b0 = x2.x * cv.x - x1.x * sv.x;
            float a1 = x1.y * cv.y + x2.y * sv.y, b1 = x2.y * cv.y - x1.y * sv.y;
            float a2 = x1.z * cv.z + x2.z * sv.z, b2 = x2.z * cv.z - x1.z * sv.z;
            float a3 = x1.w * cv.w + x2.w * sv.w, b3 = x2.w * cv.w - x1.w * sv.w;
            o1[jj] = a0; o1[jj+1] = a1; o1[jj+2] = a2; o1[jj+3] = a3;
            o2[jj] = b0; o2[jj+1] = b1; o2[jj+2] = b2; o2[jj+3] = b3;
            ss += a0*a0 + b0*b0 + a1*a1 + b1*b1 + a2*a2 + b2*b2 + a3*a3 + b3*b3;
        }
        ss += __shfl_xor_sync(0xffffffffu, ss, 1);
        const float rr = rsqrtf(ss * (1.f / 128.f) + EPS_) * scale;

        float* ob;
        if (nb < 16)
            ob = qt + (((size_t)(bb * H_ + nb) * T_ + tt) * D_);
        else
            ob = kt + (((size_t)(bb * KVH_ + (nb - 16)) * T_ + tt) * D_);

        #pragma unroll
        for (int jj = 0; jj < 32; jj += 4) {
            *(float4*)(ob + hf * 32 + jj) = make_float4(
                f2tf_f(o1[jj] * rr), f2tf_f(o1[jj+1] * rr),
                f2tf_f(o1[jj+2] * rr), f2tf_f(o1[jj+3] * rr));
            *(float4*)(ob + 64 + hf * 32 + jj) = make_float4(
                f2tf_f(o2[jj] * rr), f2tf_f(o2[jj+1] * rr),
                f2tf_f(o2[jj+2] * rr), f2tf_f(o2[jj+3] * rr));
        }
    }
}

// ---------------------------------------------------------------------------
// Plain GEMM (output projection). grid = (16, 16)
// ---------------------------------------------------------------------------
__global__ __launch_bounds__(256, 1) void out_gemm(
    const float* __restrict__ A, const float* __restrict__ W,
    float* __restrict__ C, int N)
{
    extern __shared__ unsigned sm[];

    const int tid  = threadIdx.x;
    const int lane = tid & 31;
    const int wid  = tid >> 5;
    const int g    = lane >> 2;
    const int t    = lane & 3;
    const int wm = (wid & 3) * 64;
    const int wn = (wid >> 2) * 64;
    const int m0 = blockIdx.y * 256;
    const int n0 = blockIdx.x * 128;

    const float* Ab = A + (size_t)m0 * GK;
    const float* Wb = W + (size_t)n0 * GK;

    GEMM_MAINLOOP(Ab, Wb)

    #pragma unroll
    for (int mi = 0; mi < 4; mi++) {
        int r0 = m0 + wm + mi * 16 + g;
        #pragma unroll
        for (int j = 0; j < 8; j++) {
            int cc = n0 + wn + j * 8 + 2 * t;
            *(float2*)(C + (size_t)r0 * N + cc) =
                make_float2(acc[mi][j][0], acc[mi][j][1]);
            *(float2*)(C + (size_t)(r0 + 8) * N + cc) =
                make_float2(acc[mi][j][2], acc[mi][j][3]);
        }
    }
}

// ---------------------------------------------------------------------------
// Causal flash attention v2: Q fragments in REGISTERS (loaded once),
// K/V double-buffered via cp.async (overlapped), Ps smem for P shuffle.
// ---------------------------------------------------------------------------
#define FSK 132
#define FSV 136
#define FSP 68
#define KS_W (64 * FSK)       // 8448 words per K buffer
#define VS_W (64 * FSV)       // 8704 words per V buffer
#define PS_OFF (2 * KS_W + 2 * VS_W)
#define FLASH_SMEM ((PS_OFF + 128 * FSP) * 4)   // 172032 B

__global__ __launch_bounds__(256, 1) void flash_tf32(
    const float* __restrict__ Qt, const float* __restrict__ Kt,
    const float* __restrict__ Vlin, float* __restrict__ Y)
{
    extern __shared__ unsigned smu[];

    const int tid  = threadIdx.x;
    const int lane = tid & 31;
    const int wid  = tid >> 5;
    const int g    = lane >> 2;
    const int t    = lane & 3;
    const int qb = (gridDim.x - 1) - blockIdx.x;   // heavy-first
    const int q0 = qb * 128;
    const int bh = blockIdx.y;
    const int b  = bh / H_;
    const int h  = bh % H_;
    const int kvh = h / GROUPS_;
    const int wr  = wid * 16;

    unsigned* Ps = smu + PS_OFF;
    const uint32_t sbase = smem_u32(smu);

    const float* kbase = Kt + ((size_t)(b * KVH_ + kvh) * T_) * D_;
    const float* vbase = Vlin + ((size_t)b * T_) * (KVH_ * D_) + kvh * D_;

    // ---- stage Q into smem temp (overlaps K/V buffers), then to registers --
    unsigned qreg[16][4];
    {
        const float* qbase = Qt + ((size_t)bh * T_ + q0) * D_;
        #pragma unroll
        for (int l = 0; l < 16; l++) {
            int idx = tid + l * 256;
            int r  = idx >> 5;
            int c4 = (idx & 31) * 4;
            *(uint4*)&smu[r * FSK + c4] =
                *(const uint4*)(qbase + (size_t)r * D_ + c4);
        }
        __syncthreads();
        #pragma unroll
        for (int ks = 0; ks < 16; ks++) {
            qreg[ks][0] = smu[(wr + g)     * FSK + ks * 8 + t];
            qreg[ks][1] = smu[(wr + g + 8) * FSK + ks * 8 + t];
            qreg[ks][2] = smu[(wr + g)     * FSK + ks * 8 + t + 4];
            qreg[ks][3] = smu[(wr + g + 8) * FSK + ks * 8 + t + 4];
        }
        __syncthreads();
    }

    // ---- K/V cp.async staging ----
    auto issue_kv = [&](int kt, int s) {
        const int k0 = kt * 64;
        const uint32_t kdst = sbase + (uint32_t)(s * KS_W) * 4;
        const uint32_t vdst = sbase + (uint32_t)(2 * KS_W + s * VS_W) * 4;
        #pragma unroll
        for (int l = 0; l < 8; l++) {
            int idx = tid + l * 256;
            int r  = idx >> 5;
            int c4 = (idx & 31) * 4;
            asm volatile("cp.async.cg.shared.global [%0], [%1], 16;"
                :: "r"(kdst + (uint32_t)(r * FSK + c4) * 4),
                   "l"(kbase + (size_t)(k0 + r) * D_ + c4));
            asm volatile("cp.async.cg.shared.global [%0], [%1], 16;"
                :: "r"(vdst + (uint32_t)(r * FSV + c4) * 4),
                   "l"(vbase + (size_t)(k0 + r) * (KVH_ * D_) + c4));
        }
    };

    float oacc[16][4];
    #pragma unroll
    for (int j = 0; j < 16; j++)
        #pragma unroll
        for (int c = 0; c < 4; c++) oacc[j][c] = 0.f;
    float mrow[2] = {-INFINITY, -INFINITY};
    float lrow[2] = {0.f, 0.f};

    const int nkt = qb * 2 + 2;
    issue_kv(0, 0); CPC();
    issue_kv(1, 1); CPC();

    for (int kt = 0; kt < nkt; kt++) {
        CPW1();
        __syncthreads();
        const int s = kt & 1;
        const unsigned* Kc = smu + s * KS_W;
        const unsigned* Vc = smu + 2 * KS_W + s * VS_W;
        const int k0 = kt * 64;

        // ---- S = Q . K^T  (Q from registers) ----
        float sc[8][4];
        #pragma unroll
        for (int j = 0; j < 8; j++)
            #pragma unroll
            for (int c = 0; c < 4; c++) sc[j][c] = 0.f;

        #pragma unroll
        for (int ks = 0; ks < 16; ks++) {
            #pragma unroll
            for (int j = 0; j < 8; j++) {
                unsigned kb[2];
                kb[0] = Kc[(j * 8 + g) * FSK + ks * 8 + t];
                kb[1] = Kc[(j * 8 + g) * FSK + ks * 8 + t + 4];
                mma8(sc[j], qreg[ks], kb);
            }
        }

        if (kt >= nkt - 2) {
            int row0 = q0 + wr + g;
            int row1 = row0 + 8;
            #pragma unroll
            for (int j = 0; j < 8; j++) {
                int c0 = k0 + j * 8 + 2 * t;
                int c1 = c0 + 1;
                if (c0 > row0) sc[j][0] = -1e30f;
                if (c1 > row0) sc[j][1] = -1e30f;
                if (c0 > row1) sc[j][2] = -1e30f;
                if (c1 > row1) sc[j][3] = -1e30f;
            }
        }

        #pragma unroll
        for (int ri = 0; ri < 2; ri++) {
            const int i0 = ri * 2, i1 = ri * 2 + 1;
            float mx = -1e30f;
            #pragma unroll
            for (int j = 0; j < 8; j++)
                mx = fmaxf(mx, fmaxf(sc[j][i0], sc[j][i1]));
            mx = fmaxf(mx, __shfl_xor_sync(0xffffffffu, mx, 1));
            mx = fmaxf(mx, __shfl_xor_sync(0xffffffffu, mx, 2));
            float mnew = fmaxf(mrow[ri], mx);
            float alpha = __expf(mrow[ri] - mnew);
            float rs = 0.f;
            #pragma unroll
            for (int j = 0; j < 8; j++) {
                float p0 = __expf(sc[j][i0] - mnew);
                float p1 = __expf(sc[j][i1] - mnew);
                sc[j][i0] = p0; sc[j][i1] = p1;
                rs += p0 + p1;
            }
            rs += __shfl_xor_sync(0xffffffffu, rs, 1);
            rs += __shfl_xor_sync(0xffffffffu, rs, 2);
            lrow[ri] = lrow[ri] * alpha + rs;
            mrow[ri] = mnew;
            #pragma unroll
            for (int j = 0; j < 16; j++) {
                oacc[j][i0] *= alpha;
                oacc[j][i1] *= alpha;
            }
        }

        #pragma unroll
        for (int j = 0; j < 8; j++) {
            Ps[(wr + g)     * FSP + j * 8 + 2 * t]     = f2tf(sc[j][0]);
            Ps[(wr + g)     * FSP + j * 8 + 2 * t + 1] = f2tf(sc[j][1]);
            Ps[(wr + g + 8) * FSP + j * 8 + 2 * t]     = f2tf(sc[j][2]);
            Ps[(wr + g + 8) * FSP + j * 8 + 2 * t + 1] = f2tf(sc[j][3]);
        }
        __syncwarp();

        #pragma unroll
        for (int ks = 0; ks < 8; ks++) {
            unsigned pa[4];
            pa[0] = Ps[(wr + g)     * FSP + ks * 8 + t];
            pa[1] = Ps[(wr + g + 8) * FSP + ks * 8 + t];
            pa[2] = Ps[(wr + g)     * FSP + ks * 8 + t + 4];
            pa[3] = Ps[(wr + g + 8) * FSP + ks * 8 + t + 4];
            #pragma unroll
            for (int j = 0; j < 16; j++) {
                unsigned vb[2];
                vb[0] = Vc[(ks * 8 + t)     * FSV + j * 8 + g];
                vb[1] = Vc[(ks * 8 + t + 4) * FSV + j * 8 + g];
                mma8(oacc[j], pa, vb);
            }
        }

        __syncthreads();                 // all reads of buffer s done
        if (kt + 2 < nkt) issue_kv(kt + 2, s);
        CPC();
    }

    const float il0 = 1.f / lrow[0];
    const float il1 = 1.f / lrow[1];
    float* y0 = Y + (((size_t)(b * T_ + q0 + wr + g)) * H_ + h) * D_;
    float* y1 = y0 + (size_t)8 * H_ * D_;
    #pragma unroll
    for (int j = 0; j < 16; j++) {
        int col = j * 8 + 2 * t;
        *(float2*)(y0 + col) = make_float2(f2tf_f(oacc[j][0] * il0),
                                           f2tf_f(oacc[j][1] * il0));
        *(float2*)(y1 + col) = make_float2(f2tf_f(oacc[j][2] * il1),
                                           f2tf_f(oacc[j][3] * il1));
    }
}

// ---------------------------------------------------------------------------
extern "C" void kernel_launch(void* const* d_in, const int* in_sizes, int n_in,
                              void* d_out, int out_size)
{
    const float* x    = (const float*)d_in[0];
    const float* cosb = (const float*)d_in[1];
    const float* sinb = (const float*)d_in[2];
    const float* Wq   = (const float*)d_in[3];
    const float* Wk   = (const float*)d_in[4];
    const float* Wv   = (const float*)d_in[5];
    const float* Wo   = (const float*)d_in[6];
    float* out = (float*)d_out;

    float *xc, *wqc, *wkc, *wvc, *woc, *qt, *ktp, *vlin, *y;
    cudaGetSymbolAddress((void**)&xc,   g_xc);
    cudaGetSymbolAddress((void**)&wqc,  g_wqc);
    cudaGetSymbolAddress((void**)&wkc,  g_wkc);
    cudaGetSymbolAddress((void**)&wvc,  g_wvc);
    cudaGetSymbolAddress((void**)&woc,  g_woc);
    cudaGetSymbolAddress((void**)&qt,   g_qt);
    cudaGetSymbolAddress((void**)&ktp,  g_kt);
    cudaGetSymbolAddress((void**)&vlin, g_vlin);
    cudaGetSymbolAddress((void**)&y,    g_y);

    // ---- single fused tf32 pre-convert ----
    cvt_all_kernel<<<NCVT / 256, 256>>>(
        (const float4*)x,  (float4*)xc,
        (const float4*)Wq, (float4*)wqc,
        (const float4*)Wk, (float4*)wkc,
        (const float4*)Wv, (float4*)wvc,
        (const float4*)Wo, (float4*)woc);

    cudaFuncSetAttribute(qkv_gemm, cudaFuncAttributeMaxDynamicSharedMemorySize,
                         GEMM_SMEM);
    cudaFuncSetAttribute(out_gemm, cudaFuncAttributeMaxDynamicSharedMemorySize,
                         GEMM_SMEM);
    cudaFuncSetAttribute(flash_tf32, cudaFuncAttributeMaxDynamicSharedMemorySize,
                         FLASH_SMEM);

    // Fused QKV projection + RoPE + RMSNorm + transpose
    qkv_gemm<<<dim3(24, 16), 256, GEMM_SMEM>>>(xc, wqc, wkc, wvc, cosb, sinb,
                                               qt, ktp, vlin);

    // Flash attention (Q-in-regs, cp.async K/V, heavy-first)
    flash_tf32<<<dim3(T_ / 128, B_ * H_), 256, FLASH_SMEM>>>(qt, ktp, vlin, y);

    // Output projection
    out_gemm<<<dim3(16, 16), 256, GEMM_SMEM>>>(y, woc, out, C_);
}

// round 9
// speedup vs baseline: 1.4205x; 1.0252x over previous
#include <cuda_runtime.h>
#include <math.h>
#include <stdint.h>

#define B_    2
#define T_    2048
#define C_    2048
#define H_    16
#define KVH_  4
#define D_    128
#define GROUPS_ (H_/KVH_)
#define EPS_  1.1920929e-07f

#define GK    2048
#define NIT   64

// ---------------- scratch (device globals; no cudaMalloc allowed) ----------
__device__ float g_xc  [B_*T_*C_];
__device__ float g_wqc [H_*D_*C_];
__device__ float g_wkc [KVH_*D_*C_];
__device__ float g_wvc [KVH_*D_*C_];
__device__ float g_woc [C_*C_];
__device__ float g_qt  [B_*T_*H_*D_];        // [B,H,T,D] tf32 bits (unpermuted)
__device__ float g_kt  [B_*T_*KVH_*D_];      // [B,KVH,T,D] tf32 bits, d-PERMUTED rows
__device__ float g_vperm[B_*KVH_*32*128*72]; // [B,KVH,ktile,128 d,72] tf32 bits, k-permuted
__device__ float g_y   [B_*T_*H_*D_];        // [B,T,H*D] tf32 bits

// d within an 8-group: logical loc -> stored pos 2*(loc&3) + (loc>>2)
#define PERM8(d) (((d) & 0x78) + 2*((d)&3) + (((d)>>2)&1))

// ---------------------------------------------------------------------------
// helpers
// ---------------------------------------------------------------------------
__device__ __forceinline__ unsigned f2tf(float f) {
    unsigned u;
    asm("cvt.rna.tf32.f32 %0, %1;" : "=r"(u) : "f"(f));
    return u;
}
__device__ __forceinline__ float f2tf_f(float f) {
    return __uint_as_float(f2tf(f));
}

__device__ __forceinline__ uint32_t smem_u32(const void* p) {
    uint32_t a;
    asm("{ .reg .u64 t; cvta.to.shared.u64 t, %1; cvt.u32.u64 %0, t; }"
        : "=r"(a) : "l"(p));
    return a;
}

__device__ __forceinline__ void mma8(float* d, const unsigned* a, const unsigned* b) {
    asm volatile(
        "mma.sync.aligned.m16n8k8.row.col.f32.tf32.tf32.f32 "
        "{%0,%1,%2,%3}, {%4,%5,%6,%7}, {%8,%9}, {%0,%1,%2,%3};\n"
        : "+f"(d[0]), "+f"(d[1]), "+f"(d[2]), "+f"(d[3])
        : "r"(a[0]), "r"(a[1]), "r"(a[2]), "r"(a[3]), "r"(b[0]), "r"(b[1]));
}

#define CPC()  asm volatile("cp.async.commit_group;" ::: "memory")
#define CPW1() asm volatile("cp.async.wait_group 1;" ::: "memory")

// ---------------------------------------------------------------------------
// Fused tf32 pre-convert (one launch)
// ---------------------------------------------------------------------------
#define NX4  (B_*T_*C_/4)
#define NWQ4 (H_*D_*C_/4)
#define NWK4 (KVH_*D_*C_/4)
#define NCVT (NX4 + 2*NWQ4 + 2*NWK4)

__global__ __launch_bounds__(256) void cvt_all_kernel(
    const float4* __restrict__ x,  float4* __restrict__ xc,
    const float4* __restrict__ wq, float4* __restrict__ wqc,
    const float4* __restrict__ wk, float4* __restrict__ wkc,
    const float4* __restrict__ wv, float4* __restrict__ wvc,
    const float4* __restrict__ wo, float4* __restrict__ woc)
{
    int i = blockIdx.x * 256 + threadIdx.x;
    const float4* src; float4* dst; int off;
    if (i < NX4)                         { src = x;  dst = xc;  off = 0; }
    else if (i < NX4 + NWQ4)             { src = wq; dst = wqc; off = NX4; }
    else if (i < NX4 + NWQ4 + NWK4)      { src = wk; dst = wkc; off = NX4 + NWQ4; }
    else if (i < NX4 + NWQ4 + 2*NWK4)    { src = wv; dst = wvc; off = NX4 + NWQ4 + NWK4; }
    else                                 { src = wo; dst = woc; off = NX4 + NWQ4 + 2*NWK4; }
    int j = i - off;
    float4 v = src[j];
    dst[j] = make_float4(f2tf_f(v.x), f2tf_f(v.y), f2tf_f(v.z), f2tf_f(v.w));
}

// ---------------------------------------------------------------------------
// GEMM machinery (R7/R8-proven, UNCHANGED): 256x128 CTA, BK=32, 8 warps 64x64,
// cp.async 3-stage ring, one barrier/iter, stride 36.
// ---------------------------------------------------------------------------
#define TAW (256 * 36)
#define TWW (128 * 36)
#define STGW (TAW + TWW)
#define STGB (STGW * 4)
#define GEMM_SMEM (3 * STGB)

__device__ __forceinline__ void issue_tile(uint32_t stg, const float* Ab,
                                           const float* Wb, int k0, int tid)
{
    #pragma unroll
    for (int l = 0; l < 8; l++) {
        int idx = tid + l * 256;
        int r  = idx >> 3;
        int c4 = (idx & 7) * 4;
        asm volatile("cp.async.cg.shared.global [%0], [%1], 16;"
            :: "r"(stg + (uint32_t)(r * 36 + c4) * 4),
               "l"(Ab + (size_t)r * GK + k0 + c4));
    }
    #pragma unroll
    for (int l = 0; l < 4; l++) {
        int idx = tid + l * 256;
        int r  = idx >> 3;
        int c4 = (idx & 7) * 4;
        asm volatile("cp.async.cg.shared.global [%0], [%1], 16;"
            :: "r"(stg + (uint32_t)(TAW + r * 36 + c4) * 4),
               "l"(Wb + (size_t)r * GK + k0 + c4));
    }
}

__device__ __forceinline__ void mma_tile(const unsigned* As, const unsigned* Ws,
                                         int wm, int wn, int g, int t,
                                         float acc[4][8][4]) {
    #pragma unroll
    for (int kk = 0; kk < 32; kk += 8) {
        unsigned a[4][4], b[8][2];
        #pragma unroll
        for (int mi = 0; mi < 4; mi++) {
            int r = wm + mi * 16;
            a[mi][0] = As[(r + g)     * 36 + kk + t];
            a[mi][1] = As[(r + g + 8) * 36 + kk + t];
            a[mi][2] = As[(r + g)     * 36 + kk + t + 4];
            a[mi][3] = As[(r + g + 8) * 36 + kk + t + 4];
        }
        #pragma unroll
        for (int j = 0; j < 8; j++) {
            b[j][0] = Ws[(wn + j * 8 + g) * 36 + kk + t];
            b[j][1] = Ws[(wn + j * 8 + g) * 36 + kk + t + 4];
        }
        #pragma unroll
        for (int mi = 0; mi < 4; mi++)
            #pragma unroll
            for (int j = 0; j < 8; j++)
                mma8(acc[mi][j], a[mi], b[j]);
    }
}

#define GEMM_MAINLOOP(Ab, Wb)                                                  \
    float acc[4][8][4];                                                        \
    _Pragma("unroll")                                                          \
    for (int mi = 0; mi < 4; mi++)                                             \
        _Pragma("unroll")                                                      \
        for (int j = 0; j < 8; j++)                                            \
            _Pragma("unroll")                                                  \
            for (int c = 0; c < 4; c++) acc[mi][j][c] = 0.f;                   \
    {                                                                          \
        const uint32_t sb0 = smem_u32(sm);                                     \
        issue_tile(sb0,        Ab, Wb, 0,  tid); CPC();                        \
        issue_tile(sb0 + STGB, Ab, Wb, 32, tid); CPC();                        \
        for (int it = 0; it < NIT; it++) {                                     \
            CPW1();                                                            \
            __syncthreads();                                                   \
            const int s = it - (it / 3) * 3;                                   \
            const unsigned* Ac = sm + s * STGW;                                \
            const unsigned* Wc = Ac + TAW;                                     \
            mma_tile(Ac, Wc, wm, wn, g, t, acc);                               \
            if (it + 2 < NIT) {                                                \
                const int sn = (it + 2) - ((it + 2) / 3) * 3;                  \
                issue_tile(sb0 + sn * STGB, Ab, Wb, (it + 2) * 32, tid);       \
            }                                                                  \
            CPC();                                                             \
        }                                                                      \
    }

// ---------------------------------------------------------------------------
// Fused QKV projection + RoPE + RMSNorm epilogue.
// Q: unpermuted [B,H,T,D], scale = rsqrt(D)*log2(e) folded in.
// K: [B,KVH,T,D] with PERM8 along d.
// V: scattered into g_vperm [b][kvh][ktile][d][72] (d-major, k-permuted).
// ---------------------------------------------------------------------------
__global__ __launch_bounds__(256, 1) void qkv_gemm(
    const float* __restrict__ x,
    const float* __restrict__ Wq, const float* __restrict__ Wk,
    const float* __restrict__ Wv,
    const float* __restrict__ cosb, const float* __restrict__ sinb,
    float* __restrict__ qt, float* __restrict__ kt, float* __restrict__ vperm)
{
    extern __shared__ unsigned sm[];

    const int tid  = threadIdx.x;
    const int lane = tid & 31;
    const int wid  = tid >> 5;
    const int g    = lane >> 2;
    const int t    = lane & 3;
    const int wm = (wid & 3) * 64;
    const int wn = (wid >> 2) * 64;
    const int m0 = blockIdx.y * 256;
    const int nb = blockIdx.x;

    const float* W;
    if (nb < 16)      W = Wq + (size_t)nb * 128 * GK;
    else if (nb < 20) W = Wk + (size_t)(nb - 16) * 128 * GK;
    else              W = Wv + (size_t)(nb - 20) * 128 * GK;
    const float* Ab = x + (size_t)m0 * GK;
    const float* Wb = W;

    GEMM_MAINLOOP(Ab, Wb)

    if (nb >= 20) {
        // ---- V: scatter into d-major, k-permuted blocks ----
        const int kvh = nb - 20;
        #pragma unroll
        for (int mi = 0; mi < 4; mi++) {
            #pragma unroll
            for (int half = 0; half < 2; half++) {
                int krow = m0 + wm + mi * 16 + g + half * 8;
                int bidx = krow >> 11;
                int tt   = krow & (T_ - 1);
                int ktile = tt >> 6;
                int kl    = tt & 63;
                int kp = (kl & 56) + 2 * (kl & 3) + ((kl >> 2) & 1);
                float* vb2 = vperm +
                    ((size_t)((bidx * KVH_ + kvh) * 32 + ktile) * 128) * 72 + kp;
                #pragma unroll
                for (int j = 0; j < 8; j++) {
                    int d0 = wn + j * 8 + 2 * t;
                    vb2[(size_t)d0 * 72]       = f2tf_f(acc[mi][j][half*2 + 0]);
                    vb2[(size_t)(d0 + 1) * 72] = f2tf_f(acc[mi][j][half*2 + 1]);
                }
            }
        }
        return;
    }

    __syncthreads();
    float* St = (float*)sm;
    #pragma unroll
    for (int mi = 0; mi < 4; mi++) {
        int r0 = wm + mi * 16 + g;
        #pragma unroll
        for (int j = 0; j < 8; j++) {
            int cc = wn + j * 8 + 2 * t;
            St[r0 * 132 + cc]           = acc[mi][j][0];
            St[r0 * 132 + cc + 1]       = acc[mi][j][1];
            St[(r0 + 8) * 132 + cc]     = acc[mi][j][2];
            St[(r0 + 8) * 132 + cc + 1] = acc[mi][j][3];
        }
    }
    __syncthreads();

    // Q scale folds softmax 1/sqrt(D) AND log2(e) (flash uses exp2)
    const float scale = (nb < 16) ? 0.12751744843f : 1.0f;
    #pragma unroll
    for (int round = 0; round < 2; round++) {
        const int r  = (tid >> 1) + round * 128;
        const int hf = tid & 1;
        const int m  = m0 + r;
        const int bb = m >> 11;
        const int tt = m & (T_ - 1);

        const float* cr = cosb + tt * 64 + hf * 32;
        const float* sr = sinb + tt * 64 + hf * 32;
        const float* x1p = St + r * 132 + hf * 32;
        const float* x2p = x1p + 64;

        float o1[32], o2[32];
        float ss = 0.f;
        #pragma unroll
        for (int jj = 0; jj < 32; jj += 4) {
            float4 x1 = *(const float4*)(x1p + jj);
            float4 x2 = *(const float4*)(x2p + jj);
            float4 cv = *(const float4*)(cr + jj);
            float4 sv = *(const float4*)(sr + jj);
            float a0 = x1.x * cv.x + x2.x * sv.x, b0 = x2.x * cv.x - x1.x * sv.x;
            float a1 = x1.y * cv.y + x2.y * sv.y, b1 = x2.y * cv.y - x1.y * sv.y;
            float a2 = x1.z * cv.z + x2.z * sv.z, b2 = x2.z * cv.z - x1.z * sv.z;
            float a3 = x1.w * cv.w + x2.w * sv.w, b3 = x2.w * cv.w - x1.w * sv.w;
            o1[jj] = a0; o1[jj+1] = a1; o1[jj+2] = a2; o1[jj+3] = a3;
            o2[jj] = b0; o2[jj+1] = b1; o2[jj+2] = b2; o2[jj+3] = b3;
            ss += a0*a0 + b0*b0 + a1*a1 + b1*b1 + a2*a2 + b2*b2 + a3*a3 + b3*b3;
        }
        ss += __shfl_xor_sync(0xffffffffu, ss, 1);
        const float rr = rsqrtf(ss * (1.f / 128.f) + EPS_) * scale;

        if (nb < 16) {
            float* ob = qt + (((size_t)(bb * H_ + nb) * T_ + tt) * D_);
            #pragma unroll
            for (int jj = 0; jj < 32; jj += 4) {
                *(float4*)(ob + hf * 32 + jj) = make_float4(
                    f2tf_f(o1[jj] * rr), f2tf_f(o1[jj+1] * rr),
                    f2tf_f(o1[jj+2] * rr), f2tf_f(o1[jj+3] * rr));
                *(float4*)(ob + 64 + hf * 32 + jj) = make_float4(
                    f2tf_f(o2[jj] * rr), f2tf_f(o2[jj+1] * rr),
                    f2tf_f(o2[jj+2] * rr), f2tf_f(o2[jj+3] * rr));
            }
        } else {
            float* ob = kt + (((size_t)(bb * KVH_ + (nb - 16)) * T_ + tt) * D_);
            #pragma unroll
            for (int jj = 0; jj < 32; jj++) {
                int d1 = hf * 32 + jj;
                int d2 = d1 + 64;
                ob[PERM8(d1)] = f2tf_f(o1[jj] * rr);
                ob[PERM8(d2)] = f2tf_f(o2[jj] * rr);
            }
        }
    }
}

// ---------------------------------------------------------------------------
// Plain GEMM (output projection). grid = (16, 16)
// ---------------------------------------------------------------------------
__global__ __launch_bounds__(256, 1) void out_gemm(
    const float* __restrict__ A, const float* __restrict__ W,
    float* __restrict__ C, int N)
{
    extern __shared__ unsigned sm[];

    const int tid  = threadIdx.x;
    const int lane = tid & 31;
    const int wid  = tid >> 5;
    const int g    = lane >> 2;
    const int t    = lane & 3;
    const int wm = (wid & 3) * 64;
    const int wn = (wid >> 2) * 64;
    const int m0 = blockIdx.y * 256;
    const int n0 = blockIdx.x * 128;

    const float* Ab = A + (size_t)m0 * GK;
    const float* Wb = W + (size_t)n0 * GK;

    GEMM_MAINLOOP(Ab, Wb)

    #pragma unroll
    for (int mi = 0; mi < 4; mi++) {
        int r0 = m0 + wm + mi * 16 + g;
        #pragma unroll
        for (int j = 0; j < 8; j++) {
            int cc = n0 + wn + j * 8 + 2 * t;
            *(float2*)(C + (size_t)r0 * N + cc) =
                make_float2(acc[mi][j][0], acc[mi][j][1]);
            *(float2*)(C + (size_t)(r0 + 8) * N + cc) =
                make_float2(acc[mi][j][2], acc[mi][j][3]);
        }
    }
}

// ---------------------------------------------------------------------------
// Causal flash attention v3: Q in regs, cp.async K/V double-buffered,
// ALL fragment loads LDS.64 via gmem-side k/d permutation. exp2 softmax.
// ---------------------------------------------------------------------------
#define FSK 136               // K smem row stride (136 % 32 == 8: .64-safe)
#define VST 72                // V smem row stride (d-major)
#define FSP 72                // Ps row stride
#define KBUF (64 * FSK)       // 8704 words
#define VBUF (128 * VST)      // 9216 words (matches gmem block exactly)
#define PS_OFF (2 * KBUF + 2 * VBUF)
#define FLASH_SMEM ((PS_OFF + 128 * FSP) * 4)   // 180224 B

__global__ __launch_bounds__(256, 1) void flash_tf32(
    const float* __restrict__ Qt, const float* __restrict__ Kt,
    const float* __restrict__ Vperm, float* __restrict__ Y)
{
    extern __shared__ unsigned smu[];

    const int tid  = threadIdx.x;
    const int lane = tid & 31;
    const int wid  = tid >> 5;
    const int g    = lane >> 2;
    const int t    = lane & 3;
    const int qb = (gridDim.x - 1) - blockIdx.x;   // heavy-first
    const int q0 = qb * 128;
    const int bh = blockIdx.y;
    const int b  = bh / H_;
    const int h  = bh % H_;
    const int kvh = h / GROUPS_;
    const int wr  = wid * 16;

    unsigned* Ps = smu + PS_OFF;
    const uint32_t sbase = smem_u32(smu);

    const float* kbase = Kt + ((size_t)(b * KVH_ + kvh) * T_) * D_;
    const float* vblock = Vperm + (size_t)(b * KVH_ + kvh) * 32 * VBUF;

    // Ps permuted write positions
    const int p0w = 2 * ((2 * t) & 3) + ((2 * t) >> 2);
    const int p1w = 2 * ((2 * t + 1) & 3) + ((2 * t + 1) >> 2);

    // ---- stage Q (unpermuted) into K-buffer area, then to registers ----
    unsigned qreg[16][4];
    {
        const float* qbase = Qt + ((size_t)bh * T_ + q0) * D_;
        #pragma unroll
        for (int l = 0; l < 16; l++) {
            int idx = tid + l * 256;
            int r  = idx >> 5;
            int c4 = (idx & 31) * 4;
            *(uint4*)&smu[r * 132 + c4] =
                *(const uint4*)(qbase + (size_t)r * D_ + c4);
        }
        __syncthreads();
        #pragma unroll
        for (int ks = 0; ks < 16; ks++) {
            qreg[ks][0] = smu[(wr + g)     * 132 + ks * 8 + t];
            qreg[ks][1] = smu[(wr + g + 8) * 132 + ks * 8 + t];
            qreg[ks][2] = smu[(wr + g)     * 132 + ks * 8 + t + 4];
            qreg[ks][3] = smu[(wr + g + 8) * 132 + ks * 8 + t + 4];
        }
        __syncthreads();
    }

    auto issue_kv = [&](int kt, int s) {
        const int k0 = kt * 64;
        const uint32_t kdst = sbase + (uint32_t)(s * KBUF) * 4;
        #pragma unroll
        for (int l = 0; l < 8; l++) {
            int idx = tid + l * 256;         // 64 rows x 32 chunks
            int r  = idx >> 5;
            int c4 = (idx & 31) * 4;
            asm volatile("cp.async.cg.shared.global [%0], [%1], 16;"
                :: "r"(kdst + (uint32_t)(r * FSK + c4) * 4),
                   "l"(kbase + (size_t)(k0 + r) * D_ + c4));
        }
        const float* vsrc = vblock + (size_t)kt * VBUF;
        const uint32_t vdst = sbase + (uint32_t)(2 * KBUF + s * VBUF) * 4;
        #pragma unroll
        for (int l = 0; l < 9; l++) {
            int idx = tid + l * 256;         // 2304 chunks exactly
            asm volatile("cp.async.cg.shared.global [%0], [%1], 16;"
                :: "r"(vdst + (uint32_t)idx * 16),
                   "l"(vsrc + (size_t)idx * 4));
        }
    };

    float oacc[16][4];
    #pragma unroll
    for (int j = 0; j < 16; j++)
        #pragma unroll
        for (int c = 0; c < 4; c++) oacc[j][c] = 0.f;
    float mrow[2] = {-INFINITY, -INFINITY};
    float lrow[2] = {0.f, 0.f};

    const int nkt = qb * 2 + 2;
    issue_kv(0, 0); CPC();
    issue_kv(1, 1); CPC();

    for (int kt = 0; kt < nkt; kt++) {
        CPW1();
        __syncthreads();
        const int s = kt & 1;
        const unsigned* Kc = smu + s * KBUF;
        const unsigned* Vc = smu + 2 * KBUF + s * VBUF;
        const int k0 = kt * 64;

        // ---- S = Q . K^T (Q regs; K frags via LDS.64) ----
        float sc[8][4];
        #pragma unroll
        for (int j = 0; j < 8; j++)
            #pragma unroll
            for (int c = 0; c < 4; c++) sc[j][c] = 0.f;

        #pragma unroll
        for (int ks = 0; ks < 16; ks++) {
            #pragma unroll
            for (int j = 0; j < 8; j++) {
                uint2 kv = *(const uint2*)&Kc[(j * 8 + g) * FSK + ks * 8 + 2 * t];
                unsigned kb[2] = {kv.x, kv.y};
                mma8(sc[j], qreg[ks], kb);
            }
        }

        if (kt >= nkt - 2) {
            int row0 = q0 + wr + g;
            int row1 = row0 + 8;
            #pragma unroll
            for (int j = 0; j < 8; j++) {
                int c0 = k0 + j * 8 + 2 * t;
                int c1 = c0 + 1;
                if (c0 > row0) sc[j][0] = -1e30f;
                if (c1 > row0) sc[j][1] = -1e30f;
                if (c0 > row1) sc[j][2] = -1e30f;
                if (c1 > row1) sc[j][3] = -1e30f;
            }
        }

        #pragma unroll
        for (int ri = 0; ri < 2; ri++) {
            const int i0 = ri * 2, i1 = ri * 2 + 1;
            float mx = -1e30f;
            #pragma unroll
            for (int j = 0; j < 8; j++)
                mx = fmaxf(mx, fmaxf(sc[j][i0], sc[j][i1]));
            mx = fmaxf(mx, __shfl_xor_sync(0xffffffffu, mx, 1));
            mx = fmaxf(mx, __shfl_xor_sync(0xffffffffu, mx, 2));
            float mnew = fmaxf(mrow[ri], mx);
            float alpha = exp2f(mrow[ri] - mnew);
            float rs = 0.f;
            #pragma unroll
            for (int j = 0; j < 8; j++) {
                float p0 = exp2f(sc[j][i0] - mnew);
                float p1 = exp2f(sc[j][i1] - mnew);
                sc[j][i0] = p0; sc[j][i1] = p1;
                rs += p0 + p1;
            }
            rs += __shfl_xor_sync(0xffffffffu, rs, 1);
            rs += __shfl_xor_sync(0xffffffffu, rs, 2);
            lrow[ri] = lrow[ri] * alpha + rs;
            mrow[ri] = mnew;
            #pragma unroll
            for (int j = 0; j < 16; j++) {
                oacc[j][i0] *= alpha;
                oacc[j][i1] *= alpha;
            }
        }

        // ---- write P at permuted positions ----
        #pragma unroll
        for (int j = 0; j < 8; j++) {
            Ps[(wr + g)     * FSP + j * 8 + p0w] = f2tf(sc[j][0]);
            Ps[(wr + g)     * FSP + j * 8 + p1w] = f2tf(sc[j][1]);
            Ps[(wr + g + 8) * FSP + j * 8 + p0w] = f2tf(sc[j][2]);
            Ps[(wr + g + 8) * FSP + j * 8 + p1w] = f2tf(sc[j][3]);
        }
        __syncwarp();

        // ---- O += P . V (P and V frags via LDS.64) ----
        #pragma unroll
        for (int ks = 0; ks < 8; ks++) {
            uint2 u0 = *(const uint2*)&Ps[(wr + g)     * FSP + ks * 8 + 2 * t];
            uint2 u1 = *(const uint2*)&Ps[(wr + g + 8) * FSP + ks * 8 + 2 * t];
            unsigned pa[4] = {u0.x, u1.x, u0.y, u1.y};
            #pragma unroll
            for (int j = 0; j < 16; j++) {
                uint2 vv = *(const uint2*)&Vc[(j * 8 + g) * VST + ks * 8 + 2 * t];
                unsigned vb[2] = {vv.x, vv.y};
                mma8(oacc[j], pa, vb);
            }
        }

        __syncthreads();
        if (kt + 2 < nkt) issue_kv(kt + 2, s);
        CPC();
    }

    const float il0 = 1.f / lrow[0];
    const float il1 = 1.f / lrow[1];
    float* y0 = Y + (((size_t)(b * T_ + q0 + wr + g)) * H_ + h) * D_;
    float* y1 = y0 + (size_t)8 * H_ * D_;
    #pragma unroll
    for (int j = 0; j < 16; j++) {
        int col = j * 8 + 2 * t;
        *(float2*)(y0 + col) = make_float2(f2tf_f(oacc[j][0] * il0),
                                           f2tf_f(oacc[j][1] * il0));
        *(float2*)(y1 + col) = make_float2(f2tf_f(oacc[j][2] * il1),
                                           f2tf_f(oacc[j][3] * il1));
    }
}

// ---------------------------------------------------------------------------
extern "C" void kernel_launch(void* const* d_in, const int* in_sizes, int n_in,
                              void* d_out, int out_size)
{
    const float* x    = (const float*)d_in[0];
    const float* cosb = (const float*)d_in[1];
    const float* sinb = (const float*)d_in[2];
    const float* Wq   = (const float*)d_in[3];
    const float* Wk   = (const float*)d_in[4];
    const float* Wv   = (const float*)d_in[5];
    const float* Wo   = (const float*)d_in[6];
    float* out = (float*)d_out;

    float *xc, *wqc, *wkc, *wvc, *woc, *qt, *ktp, *vperm, *y;
    cudaGetSymbolAddress((void**)&xc,    g_xc);
    cudaGetSymbolAddress((void**)&wqc,   g_wqc);
    cudaGetSymbolAddress((void**)&wkc,   g_wkc);
    cudaGetSymbolAddress((void**)&wvc,   g_wvc);
    cudaGetSymbolAddress((void**)&woc,   g_woc);
    cudaGetSymbolAddress((void**)&qt,    g_qt);
    cudaGetSymbolAddress((void**)&ktp,   g_kt);
    cudaGetSymbolAddress((void**)&vperm, g_vperm);
    cudaGetSymbolAddress((void**)&y,     g_y);

    cvt_all_kernel<<<NCVT / 256, 256>>>(
        (const float4*)x,  (float4*)xc,
        (const float4*)Wq, (float4*)wqc,
        (const float4*)Wk, (float4*)wkc,
        (const float4*)Wv, (float4*)wvc,
        (const float4*)Wo, (float4*)woc);

    cudaFuncSetAttribute(qkv_gemm, cudaFuncAttributeMaxDynamicSharedMemorySize,
                         GEMM_SMEM);
    cudaFuncSetAttribute(out_gemm, cudaFuncAttributeMaxDynamicSharedMemorySize,
                         GEMM_SMEM);
    cudaFuncSetAttribute(flash_tf32, cudaFuncAttributeMaxDynamicSharedMemorySize,
                         FLASH_SMEM);

    qkv_gemm<<<dim3(24, 16), 256, GEMM_SMEM>>>(xc, wqc, wkc, wvc, cosb, sinb,
                                               qt, ktp, vperm);

    flash_tf32<<<dim3(T_ / 128, B_ * H_), 256, FLASH_SMEM>>>(qt, ktp, vperm, y);

    out_gemm<<<dim3(16, 16), 256, GEMM_SMEM>>>(y, woc, out, C_);
}